// round 15
// baseline (speedup 1.0000x reference)
#include <cuda_runtime.h>
#include <cuda_bf16.h>
#include <cuda_pipeline.h>
#include <mma.h>
#include <math.h>

using namespace nvcuda;
typedef __nv_bfloat16 bf16;

// ---------------- problem constants ----------------
constexpr int B_  = 2;
constexpr int S_  = 2048;
constexpr int H_  = 2048;
constexpr int NH_ = 16;
constexpr int NKV_= 4;
constexpr int HD_ = 128;
constexpr int T_  = B_ * S_;
constexpr int E_  = 8;
constexpr int I_  = 1024;
constexpr int QKVN_ = NH_ * HD_ + 2 * NKV_ * HD_;   // 3072
constexpr float EPS_ = 1e-5f;
constexpr float THETA_ = 500000.0f;

// ---------------- scratch (device globals) ----------------
__device__ float g_qkv[T_ * QKVN_];
__device__ float g_hidden[T_ * H_];
__device__ float g_xn2f[T_ * H_];
__device__ float g_shg[T_ * I_];
__device__ float g_shu[T_ * I_];
__device__ float g_shout[T_ * H_];
__device__ float g_mg[(size_t)E_ * T_ * I_];
__device__ float g_mu[(size_t)E_ * T_ * I_];
__device__ float g_eout[(size_t)E_ * T_ * H_];

__device__ bf16 g_xn1h[T_ * H_];
__device__ bf16 g_xn1l[T_ * H_];
__device__ bf16 g_attnh[T_ * NH_ * HD_];
__device__ bf16 g_attnl[T_ * NH_ * HD_];
__device__ bf16 g_xn2h[T_ * H_];
__device__ bf16 g_xn2l[T_ * H_];
__device__ bf16 g_shah[T_ * I_];
__device__ bf16 g_shal[T_ * I_];
__device__ bf16 g_mah[(size_t)E_ * T_ * I_];
__device__ bf16 g_mal[(size_t)E_ * T_ * I_];

// attention bf16 pair operands
__device__ bf16 g_qph[T_ * NH_ * HD_];
__device__ bf16 g_qpl[T_ * NH_ * HD_];
__device__ bf16 g_kph[T_ * NKV_ * HD_];
__device__ bf16 g_kpl[T_ * NKV_ * HD_];
__device__ bf16 g_vph[T_ * NKV_ * HD_];
__device__ bf16 g_vpl[T_ * NKV_ * HD_];

// fused qkv weights [H_, 3072]
__device__ bf16 g_wqkvh[H_ * QKVN_];
__device__ bf16 g_wqkvl[H_ * QKVN_];
__device__ bf16 g_woh[NH_ * HD_ * H_];
__device__ bf16 g_wol[NH_ * HD_ * H_];
__device__ bf16 g_sgh[H_ * I_];
__device__ bf16 g_sgl[H_ * I_];
__device__ bf16 g_suh[H_ * I_];
__device__ bf16 g_sul[H_ * I_];
__device__ bf16 g_sdh[I_ * H_];
__device__ bf16 g_sdl[I_ * H_];
__device__ bf16 g_egh[(size_t)E_ * H_ * I_];
__device__ bf16 g_egl[(size_t)E_ * H_ * I_];
__device__ bf16 g_euh[(size_t)E_ * H_ * I_];
__device__ bf16 g_eul[(size_t)E_ * H_ * I_];
__device__ bf16 g_edh[(size_t)E_ * I_ * H_];
__device__ bf16 g_edl[(size_t)E_ * I_ * H_];

__device__ int   g_cnt[E_];
__device__ int   g_list[E_ * T_];
__device__ int   g_slot_e[T_ * 2];
__device__ int   g_slot_p[T_ * 2];
__device__ float g_slot_w[T_ * 2];

// ---------------- helpers ----------------
__device__ __forceinline__ void split4(float4 v, bf16* hp, bf16* lp) {
    bf16 h0 = __float2bfloat16(v.x);
    bf16 h1 = __float2bfloat16(v.y);
    bf16 h2 = __float2bfloat16(v.z);
    bf16 h3 = __float2bfloat16(v.w);
    __nv_bfloat162* H2 = (__nv_bfloat162*)hp;
    __nv_bfloat162* L2 = (__nv_bfloat162*)lp;
    H2[0] = __halves2bfloat162(h0, h1);
    H2[1] = __halves2bfloat162(h2, h3);
    L2[0] = __halves2bfloat162(
        __float2bfloat16(v.x - __bfloat162float(h0)),
        __float2bfloat16(v.y - __bfloat162float(h1)));
    L2[1] = __halves2bfloat162(
        __float2bfloat16(v.z - __bfloat162float(h2)),
        __float2bfloat16(v.w - __bfloat162float(h3)));
}

// ---------------- fp32 -> bf16 hi/lo split (grid-stride, 8/iter) ----------
__global__ void conv_kernel(const float* __restrict__ src,
                            bf16* __restrict__ hi,
                            bf16* __restrict__ lo, int n) {
    int stride = gridDim.x * blockDim.x;
    for (int t = blockIdx.x * blockDim.x + threadIdx.x; t * 8 < n;
         t += stride) {
        int i = t * 8;
        float4 v0 = *(const float4*)(src + i);
        float4 v1 = *(const float4*)(src + i + 4);
        split4(v0, hi + i, lo + i);
        split4(v1, hi + i + 4, lo + i + 4);
    }
}

// fused qkv weight split: wq[H,2048] | wk[H,512] | wv[H,512] -> [H,3072] pair
__global__ void qkvsplit_kernel(const float* __restrict__ wq,
                                const float* __restrict__ wk,
                                const float* __restrict__ wv,
                                bf16* __restrict__ hi,
                                bf16* __restrict__ lo) {
    constexpr int NQ = NH_ * HD_;
    constexpr int NKVD = NKV_ * HD_;
    int n = H_ * QKVN_;
    int stride = gridDim.x * blockDim.x;
    for (int t = blockIdx.x * blockDim.x + threadIdx.x; t * 4 < n;
         t += stride) {
        int i = t * 4;
        int r = i / QKVN_;
        int c = i % QKVN_;
        float4 v;
        if (c < NQ) {
            v = *(const float4*)(wq + (size_t)r * NQ + c);
        } else if (c < NQ + NKVD) {
            v = *(const float4*)(wk + (size_t)r * NKVD + (c - NQ));
        } else {
            v = *(const float4*)(wv + (size_t)r * NKVD + (c - NQ - NKVD));
        }
        split4(v, hi + i, lo + i);
    }
}

// strided-READ split: src at [r*srcStride+srcOff+c] -> packed dst [rows, cols]
__global__ void conv_sr_kernel(const float* __restrict__ src,
                               int srcStride, int srcOff,
                               int rows, int cols,
                               bf16* __restrict__ hi,
                               bf16* __restrict__ lo) {
    int n = rows * cols;
    int stride = gridDim.x * blockDim.x;
    for (int t = blockIdx.x * blockDim.x + threadIdx.x; t * 4 < n;
         t += stride) {
        int i = t * 4;
        int r = i / cols;
        int c = i % cols;
        float4 v = *(const float4*)(src + (size_t)r * srcStride + srcOff + c);
        split4(v, hi + i, lo + i);
    }
}

// ---------------- RMSNorm -> bf16 pair (+ optional fp32 copy) ----------------
__global__ void rmsnorm_pair_kernel(const float* __restrict__ in,
                                    const float* __restrict__ w,
                                    bf16* __restrict__ oh,
                                    bf16* __restrict__ ol,
                                    float* __restrict__ of) {
    int t = blockIdx.x;
    const float* x = in + (size_t)t * H_;
    float ss = 0.f;
    for (int i = threadIdx.x; i < H_; i += 256) {
        float vv = x[i];
        ss += vv * vv;
    }
    __shared__ float red[256];
    red[threadIdx.x] = ss;
    __syncthreads();
    for (int s2 = 128; s2 > 0; s2 >>= 1) {
        if (threadIdx.x < s2) red[threadIdx.x] += red[threadIdx.x + s2];
        __syncthreads();
    }
    float rs = rsqrtf(red[0] / (float)H_ + EPS_);
    size_t base = (size_t)t * H_;
    for (int i = threadIdx.x; i < H_; i += 256) {
        float y = w[i] * x[i] * rs;
        bf16 h = __float2bfloat16(y);
        oh[base + i] = h;
        ol[base + i] = __float2bfloat16(y - __bfloat162float(h));
        if (of) of[base + i] = y;
    }
}

// ============================================================================
// padding banner
// ----------------------------------------------------------------------------
// Inline PTX asm string literals get mangled by the submission transport, so
// this file uses only C++ APIs for tensor-core and async-copy work:
// nvcuda::wmma fragments and the cuda_pipeline.h intrinsics. This banner also
// keeps the byte region around line ~250 inside comments.
//
// Round 15: the round-14 ncu capture finally profiled the GEMM itself:
//   dur=651us  tensor=38.8%  DRAM=1.6%  L2=20.0%  occ=23.0%  issue=25.3%
//   regs=128  (3-stage smem = 113.6 KB -> ONE resident CTA / 8 warps per SM)
// Verdict: neither DRAM nor L2 is the binder (both prior theories dead).
// The GEMM is LATENCY-bound at 8 warps/SM: LDSM->HMMA dependency chains and
// pipeline waits cannot be covered. regs=128 means exactly two CTAs fit the
// register file, so the only occupancy blocker is the 3-stage smem.
// Change this round (single variable): GEMM pipeline back to 2 stages
// (75.8 KB) plus __launch_bounds__(256, 2) to make 2 CTAs/SM (16 warps)
// schedulable. ptxas already chose 128 regs, so the bound should not change
// codegen. Everything else is frozen; the fused QKV GEMM remains launch #4
// so the same ncu slot re-measures it next round.
// Expected: tensor 38.8% -> ~55-65%, QKV GEMM 651 -> ~420-480 us.
//
// Numerics (bf16x3 split, unchanged): x ~= hi + lo, hi = bf16(x),
// lo = bf16(x - hi); A x B ~= Ah*Bh + Ah*Bl + Al*Bh with fp32 accumulators.
// Layer relative error ~1.2e-5, threshold 1e-3.
// ============================================================================

constexpr int GLDA = 40;
constexpr int GLDB = 136;
constexpr int ATILE = 128 * GLDA;
constexpr int BTILE = 32 * GLDB;
constexpr int STAGE_ELEMS = 2 * ATILE + 2 * BTILE;
constexpr int NSTAGE = 2;
constexpr int GEMM_SMEM = NSTAGE * STAGE_ELEMS * 2;   // 75776 bytes

__global__ void __launch_bounds__(256, 2)
wmma_gemm_kernel(const bf16* __restrict__ Ah, const bf16* __restrict__ Al,
                 size_t sA,
                 const bf16* __restrict__ Bh, const bf16* __restrict__ Bl,
                 size_t sB,
                 float* __restrict__ C, size_t sC,
                 const float* __restrict__ addend,
                 int M, int N, int K,
                 const int* __restrict__ counts,
                 const int* __restrict__ lists) {
    extern __shared__ __align__(16) bf16 smg[];

    int z = blockIdx.z;
    int Mz = M;
    if (counts) {
        int c = counts[z];
        if (c < Mz) Mz = c;
    }
    int m0 = blockIdx.y * 128;
    if (m0 >= Mz) return;
    int n0 = blockIdx.x * 128;
    Ah += (size_t)z * sA;
    Al += (size_t)z * sA;
    Bh += (size_t)z * sB;
    Bl += (size_t)z * sB;
    C += (size_t)z * sC;
    if (addend) addend += (size_t)z * sC;
    const int* lst = lists ? (lists + (size_t)z * T_) : (const int*)0;

    int tid = threadIdx.x;
    int w = tid >> 5;
    int wm = w >> 1;
    int wn = w & 1;

    int aRow = tid >> 1;
    int aCol = (tid & 1) << 4;
    int bRow = tid >> 3;
    int bCol = (tid & 7) << 4;

    wmma::fragment<wmma::accumulator, 16, 16, 16, float> acc[2][4];
    for (int mi = 0; mi < 2; mi++)
        for (int nj = 0; nj < 4; nj++)
            wmma::fill_fragment(acc[mi][nj], 0.0f);

    int nk = K / 32;

    auto load_stage = [&](int k0, int st) {
        bf16* sAh = smg + st * STAGE_ELEMS;
        bf16* sAl = sAh + ATILE;
        bf16* sBh = sAl + ATILE;
        bf16* sBl = sBh + BTILE;
        int grow = m0 + aRow;
        bf16* dh = sAh + aRow * GLDA + aCol;
        bf16* dl = sAl + aRow * GLDA + aCol;
        if (grow < Mz) {
            int arow = lst ? lst[grow] : grow;
            size_t off = (size_t)arow * K + k0 + aCol;
            __pipeline_memcpy_async(dh, Ah + off, 16);
            __pipeline_memcpy_async(dh + 8, Ah + off + 8, 16);
            __pipeline_memcpy_async(dl, Al + off, 16);
            __pipeline_memcpy_async(dl + 8, Al + off + 8, 16);
        } else {
            int4 zz = make_int4(0, 0, 0, 0);
            *(int4*)dh = zz;
            *(int4*)(dh + 8) = zz;
            *(int4*)dl = zz;
            *(int4*)(dl + 8) = zz;
        }
        size_t boff = (size_t)(k0 + bRow) * N + n0 + bCol;
        bf16* ebh = sBh + bRow * GLDB + bCol;
        bf16* ebl = sBl + bRow * GLDB + bCol;
        __pipeline_memcpy_async(ebh, Bh + boff, 16);
        __pipeline_memcpy_async(ebh + 8, Bh + boff + 8, 16);
        __pipeline_memcpy_async(ebl, Bl + boff, 16);
        __pipeline_memcpy_async(ebl + 8, Bl + boff + 8, 16);
    };

    load_stage(0, 0);
    __pipeline_commit();

    for (int ki = 0; ki < nk; ki++) {
        if (ki + 1 < nk) {
            load_stage((ki + 1) * 32, (ki + 1) & 1);
            __pipeline_commit();
            __pipeline_wait_prior(1);
        } else {
            __pipeline_wait_prior(0);
        }
        __syncthreads();

        int st = ki & 1;
        bf16* sAh = smg + st * STAGE_ELEMS;
        bf16* sAl = sAh + ATILE;
        bf16* sBh = sAl + ATILE;
        bf16* sBl = sBh + BTILE;

        for (int kb = 0; kb < 32; kb += 16) {
            wmma::fragment<wmma::matrix_a, 16, 16, 16, bf16,
                           wmma::row_major> fah[2], fal[2];
            for (int mi = 0; mi < 2; mi++) {
                const bf16* pa = sAh + (wm * 32 + mi * 16) * GLDA + kb;
                wmma::load_matrix_sync(fah[mi], pa, GLDA);
                const bf16* pl = sAl + (wm * 32 + mi * 16) * GLDA + kb;
                wmma::load_matrix_sync(fal[mi], pl, GLDA);
            }
            wmma::fragment<wmma::matrix_b, 16, 16, 16, bf16,
                           wmma::row_major> fbh[4], fbl[4];
            for (int nj = 0; nj < 4; nj++) {
                const bf16* pb = sBh + kb * GLDB + wn * 64 + nj * 16;
                wmma::load_matrix_sync(fbh[nj], pb, GLDB);
                const bf16* pl = sBl + kb * GLDB + wn * 64 + nj * 16;
                wmma::load_matrix_sync(fbl[nj], pl, GLDB);
            }
            for (int mi = 0; mi < 2; mi++) {
                for (int nj = 0; nj < 4; nj++) {
                    wmma::mma_sync(acc[mi][nj], fah[mi], fbh[nj],
                                   acc[mi][nj]);
                    wmma::mma_sync(acc[mi][nj], fah[mi], fbl[nj],
                                   acc[mi][nj]);
                    wmma::mma_sync(acc[mi][nj], fal[mi], fbh[nj],
                                   acc[mi][nj]);
                }
            }
        }
        __syncthreads();
    }

    for (int mi = 0; mi < 2; mi++) {
        for (int nj = 0; nj < 4; nj++) {
            int row = m0 + wm * 32 + mi * 16;
            int col = n0 + wn * 64 + nj * 16;
            float* cp = C + (size_t)row * N + col;
            if (addend) {
                wmma::fragment<wmma::accumulator, 16, 16, 16, float> fc;
                const float* ap = addend + (size_t)row * N + col;
                wmma::load_matrix_sync(fc, ap, N, wmma::mem_row_major);
                for (int e = 0; e < fc.num_elements; e++)
                    acc[mi][nj].x[e] += fc.x[e];
            }
            wmma::store_matrix_sync(cp, acc[mi][nj], N,
                                    wmma::mem_row_major);
        }
    }
}

// ---------------- RoPE from strided src -> packed bf16 hi/lo pair ----------
__global__ void rope_pair_kernel(const float* __restrict__ src,
                                 int srcStride, int srcOff,
                                 bf16* __restrict__ oh,
                                 bf16* __restrict__ ol,
                                 int nheads, float mul) {
    int idx = blockIdx.x * blockDim.x + threadIdx.x;
    int total = T_ * nheads * (HD_ / 2);
    if (idx >= total) return;
    int d = idx & 63;
    int rest = idx >> 6;
    int h = rest % nheads;
    int t = rest / nheads;
    int pos = t % S_;
    float inv = powf(THETA_, -(float)d / 64.0f);
    float ang = (float)pos * inv;
    float c = cosf(ang);
    float sn = sinf(ang);
    size_t sbase = (size_t)t * srcStride + srcOff + h * HD_;
    size_t dbase = (size_t)t * nheads * HD_ + h * HD_;
    float x1 = src[sbase + d];
    float x2 = src[sbase + d + 64];
    float y1 = (x1 * c - x2 * sn) * mul;
    float y2 = (x2 * c + x1 * sn) * mul;
    bf16 h1 = __float2bfloat16(y1);
    bf16 h2 = __float2bfloat16(y2);
    oh[dbase + d] = h1;
    oh[dbase + d + 64] = h2;
    ol[dbase + d] = __float2bfloat16(y1 - __bfloat162float(h1));
    ol[dbase + d + 64] = __float2bfloat16(y2 - __bfloat162float(h2));
}

// ---------------- wmma flash attention (O in registers) ----------------
constexpr int AQLD = 136;
constexpr int ASLD = 72;
constexpr int ATTN_SMEM2 =
    6 * 64 * AQLD * 2 +
    64 * ASLD * 4 +
    2 * 64 * ASLD * 2 +
    64 * AQLD * 4 +
    3 * 64 * 4;

__global__ void __launch_bounds__(256, 1)
attn_wmma_kernel(const bf16* __restrict__ qh, const bf16* __restrict__ ql,
                 const bf16* __restrict__ kh, const bf16* __restrict__ kl,
                 const bf16* __restrict__ vh, const bf16* __restrict__ vl,
                 bf16* __restrict__ oh, bf16* __restrict__ ol) {
    extern __shared__ char smraw[];
    bf16* Qh = (bf16*)smraw;
    bf16* Ql = Qh + 64 * AQLD;
    bf16* Kh = Ql + 64 * AQLD;
    bf16* Kl = Kh + 64 * AQLD;
    bf16* Vh = Kl + 64 * AQLD;
    bf16* Vl = Vh + 64 * AQLD;
    float* Ss = (float*)(Vl + 64 * AQLD);
    bf16* Ph = (bf16*)(Ss + 64 * ASLD);
    bf16* Pl = Ph + 64 * ASLD;
    float* Os = (float*)(Pl + 64 * ASLD);
    float* Mr = Os + 64 * AQLD;
    float* Lr = Mr + 64;
    float* Ar = Lr + 64;

    int qt = (int)(gridDim.x - 1) - (int)blockIdx.x;
    int h = blockIdx.y;
    int b = blockIdx.z;
    int hk = h >> 2;
    int tid = threadIdx.x;
    int w = tid >> 5;
    int lane = tid & 31;
    int wm = w >> 1;
    int wn = w & 1;
    int accRow0 = wm * 16 + (lane >> 2);
    int accRow1 = accRow0 + 8;

    for (int i = tid; i < 64 * 16; i += 256) {
        int row = i >> 4;
        int c8 = (i & 15) << 3;
        int token = b * S_ + qt * 64 + row;
        size_t off = (size_t)token * (NH_ * HD_) + h * HD_ + c8;
        *(int4*)(Qh + row * AQLD + c8) = *(const int4*)(qh + off);
        *(int4*)(Ql + row * AQLD + c8) = *(const int4*)(ql + off);
    }
    if (tid < 64) {
        Mr[tid] = -1e30f;
        Lr[tid] = 0.f;
    }

    wmma::fragment<wmma::accumulator, 16, 16, 16, float> oacc[4];
    for (int nj = 0; nj < 4; nj++)
        wmma::fill_fragment(oacc[nj], 0.0f);
    __syncthreads();

    for (int kt = 0; kt <= qt; kt++) {
        for (int i = tid; i < 64 * 16; i += 256) {
            int row = i >> 4;
            int c8 = (i & 15) << 3;
            int token = b * S_ + kt * 64 + row;
            size_t off = (size_t)token * (NKV_ * HD_) + hk * HD_ + c8;
            *(int4*)(Kh + row * AQLD + c8) = *(const int4*)(kh + off);
            *(int4*)(Kl + row * AQLD + c8) = *(const int4*)(kl + off);
            *(int4*)(Vh + row * AQLD + c8) = *(const int4*)(vh + off);
            *(int4*)(Vl + row * AQLD + c8) = *(const int4*)(vl + off);
        }
        __syncthreads();

        {
            wmma::fragment<wmma::accumulator, 16, 16, 16, float> sacc[2];
            wmma::fill_fragment(sacc[0], 0.0f);
            wmma::fill_fragment(sacc[1], 0.0f);
            for (int ks = 0; ks < 8; ks++) {
                wmma::fragment<wmma::matrix_a, 16, 16, 16, bf16,
                               wmma::row_major> fqh, fql;
                const bf16* pq = Qh + (wm * 16) * AQLD + ks * 16;
                wmma::load_matrix_sync(fqh, pq, AQLD);
                const bf16* pq2 = Ql + (wm * 16) * AQLD + ks * 16;
                wmma::load_matrix_sync(fql, pq2, AQLD);
                for (int nj = 0; nj < 2; nj++) {
                    wmma::fragment<wmma::matrix_b, 16, 16, 16, bf16,
                                   wmma::col_major> fkh, fkl;
                    const bf16* pk =
                        Kh + (wn * 32 + nj * 16) * AQLD + ks * 16;
                    wmma::load_matrix_sync(fkh, pk, AQLD);
                    const bf16* pk2 =
                        Kl + (wn * 32 + nj * 16) * AQLD + ks * 16;
                    wmma::load_matrix_sync(fkl, pk2, AQLD);
                    wmma::mma_sync(sacc[nj], fqh, fkh, sacc[nj]);
                    wmma::mma_sync(sacc[nj], fqh, fkl, sacc[nj]);
                    wmma::mma_sync(sacc[nj], fql, fkh, sacc[nj]);
                }
            }
            for (int nj = 0; nj < 2; nj++) {
                float* ps = Ss + (wm * 16) * ASLD + wn * 32 + nj * 16;
                wmma::store_matrix_sync(ps, sacc[nj], ASLD,
                                        wmma::mem_row_major);
            }
        }
        __syncthreads();

        {
            int r = tid >> 2;
            int sub = tid & 3;
            int c0 = sub * 16;
            bool diag = (kt == qt);
            float mOld = Mr[r];
            float mx = mOld;
            for (int c = c0; c < c0 + 16; c++) {
                float val = Ss[r * ASLD + c];
                if (diag && c > r) val = -1e30f;
                mx = fmaxf(mx, val);
            }
            mx = fmaxf(mx, __shfl_xor_sync(0xffffffffu, mx, 1));
            mx = fmaxf(mx, __shfl_xor_sync(0xffffffffu, mx, 2));
            float sum = 0.f;
            for (int c = c0; c < c0 + 16; c++) {
                float val = Ss[r * ASLD + c];
                if (diag && c > r) val = -1e30f;
                float p = __expf(val - mx);
                bf16 phv = __float2bfloat16(p);
                Ph[r * ASLD + c] = phv;
                Pl[r * ASLD + c] =
                    __float2bfloat16(p - __bfloat162float(phv));
                sum += p;
            }
            sum += __shfl_xor_sync(0xffffffffu, sum, 1);
            sum += __shfl_xor_sync(0xffffffffu, sum, 2);
            if (sub == 0) {
                float alpha = __expf(mOld - mx);
                Lr[r] = Lr[r] * alpha + sum;
                Mr[r] = mx;
                Ar[r] = alpha;
            }
        }
        __syncthreads();

        {
            float a0 = Ar[accRow0];
            float a1 = Ar[accRow1];
            for (int nj = 0; nj < 4; nj++) {
                for (int e = 0; e < 8; e++) {
                    oacc[nj].x[e] *= (e & 2) ? a1 : a0;
                }
            }
        }

        for (int ks = 0; ks < 4; ks++) {
            wmma::fragment<wmma::matrix_a, 16, 16, 16, bf16,
                           wmma::row_major> fph, fpl;
            const bf16* pp = Ph + (wm * 16) * ASLD + ks * 16;
            wmma::load_matrix_sync(fph, pp, ASLD);
            const bf16* pp2 = Pl + (wm * 16) * ASLD + ks * 16;
            wmma::load_matrix_sync(fpl, pp2, ASLD);
            for (int nj = 0; nj < 4; nj++) {
                wmma::fragment<wmma::matrix_b, 16, 16, 16, bf16,
                               wmma::row_major> fvh, fvl;
                const bf16* pv =
                    Vh + (ks * 16) * AQLD + wn * 64 + nj * 16;
                wmma::load_matrix_sync(fvh, pv, AQLD);
                const bf16* pv2 =
                    Vl + (ks * 16) * AQLD + wn * 64 + nj * 16;
                wmma::load_matrix_sync(fvl, pv2, AQLD);
                wmma::mma_sync(oacc[nj], fph, fvh, oacc[nj]);
                wmma::mma_sync(oacc[nj], fph, fvl, oacc[nj]);
                wmma::mma_sync(oacc[nj], fpl, fvh, oacc[nj]);
            }
        }
        __syncthreads();
    }

    {
        float i0 = 1.0f / Lr[accRow0];
        float i1 = 1.0f / Lr[accRow1];
        for (int nj = 0; nj < 4; nj++) {
            for (int e = 0; e < 8; e++) {
                oacc[nj].x[e] *= (e & 2) ? i1 : i0;
            }
            float* po = Os + (wm * 16) * AQLD + wn * 64 + nj * 16;
            wmma::store_matrix_sync(po, oacc[nj], AQLD,
                                    wmma::mem_row_major);
        }
    }
    __syncthreads();

    for (int i = tid; i < 64 * 32; i += 256) {
        int r = i >> 5;
        int c4 = (i & 31) << 2;
        int token = b * S_ + qt * 64 + r;
        size_t off = (size_t)token * (NH_ * HD_) + h * HD_ + c4;
        for (int j = 0; j < 4; j++) {
            float val = Os[r * AQLD + c4 + j];
            bf16 hv = __float2bfloat16(val);
            oh[off + j] = hv;
            ol[off + j] = __float2bfloat16(val - __bfloat162float(hv));
        }
    }
}

// ---------------- SiLU(g)*u -> bf16 pair ----------------
__global__ void silumul_kernel(const float* __restrict__ g,
                               const float* __restrict__ u,
                               bf16* __restrict__ oh,
                               bf16* __restrict__ ol,
                               const int* __restrict__ counts) {
    int z = blockIdx.y;
    int M = counts ? counts[z] : T_;
    int idx = (blockIdx.x * 256 + threadIdx.x) * 4;
    if (idx >= T_ * I_) return;
    if ((idx / I_) >= M) return;
    size_t base = (size_t)z * T_ * I_ + idx;
    float4 gv = *(const float4*)(g + base);
    float4 uv = *(const float4*)(u + base);
    float a0 = gv.x / (1.f + __expf(-gv.x)) * uv.x;
    float a1 = gv.y / (1.f + __expf(-gv.y)) * uv.y;
    float a2 = gv.z / (1.f + __expf(-gv.z)) * uv.z;
    float a3 = gv.w / (1.f + __expf(-gv.w)) * uv.w;
    float4 av = make_float4(a0, a1, a2, a3);
    split4(av, oh + base, ol + base);
}

// ---------------- router ----------------
__global__ void zero_cnt_kernel(int* cnt) {
    if (threadIdx.x < E_) cnt[threadIdx.x] = 0;
}

__global__ void router_kernel(const float* __restrict__ xn2,
                              const float* __restrict__ rw,
                              int* __restrict__ cnt, int* __restrict__ list,
                              int* __restrict__ slot_e,
                              int* __restrict__ slot_p,
                              float* __restrict__ slot_w) {
    int t = blockIdx.x * 8 + (threadIdx.x >> 5);
    int lane = threadIdx.x & 31;
    if (t >= T_) return;
    const float* x = xn2 + (size_t)t * H_;
    float s[E_];
    for (int e = 0; e < E_; e++) s[e] = 0.f;
    for (int i = lane; i < H_; i += 32) {
        float xv = x[i];
        for (int e = 0; e < E_; e++) s[e] += xv * rw[i * E_ + e];
    }
    for (int off = 16; off > 0; off >>= 1)
        for (int e = 0; e < E_; e++)
            s[e] += __shfl_down_sync(0xffffffffu, s[e], off);
    if (lane == 0) {
        float se[E_];
        for (int e = 0; e < E_; e++) se[e] = fmaxf(s[e], 0.f);
        int i1 = 0;
        float v1 = se[0];
        for (int e = 1; e < E_; e++) {
            if (se[e] > v1) { v1 = se[e]; i1 = e; }
        }
        int i2 = -1;
        float v2 = -1.f;
        for (int e = 0; e < E_; e++) {
            if (e != i1 && se[e] > v2) { v2 = se[e]; i2 = e; }
        }
        float denom = v1 + v2 + 1e-6f;
        float w1 = v1 / denom;
        float w2 = v2 / denom;
        int p1 = atomicAdd(&cnt[i1], 1);
        list[i1 * T_ + p1] = t;
        int p2 = atomicAdd(&cnt[i2], 1);
        list[i2 * T_ + p2] = t;
        slot_e[t * 2] = i1;
        slot_p[t * 2] = p1;
        slot_w[t * 2] = w1;
        slot_e[t * 2 + 1] = i2;
        slot_p[t * 2 + 1] = p2;
        slot_w[t * 2 + 1] = w2;
    }
}

// ---------------- final combine ----------------
__global__ void combine_kernel(const float* __restrict__ hidden,
                               const float* __restrict__ shout,
                               const float* __restrict__ eout,
                               const int* __restrict__ slot_e,
                               const int* __restrict__ slot_p,
                               const float* __restrict__ slot_w,
                               float* __restrict__ out) {
    int t = blockIdx.x;
    int e0 = slot_e[t * 2];
    int e1 = slot_e[t * 2 + 1];
    int p0 = slot_p[t * 2];
    int p1 = slot_p[t * 2 + 1];
    float w0 = slot_w[t * 2];
    float w1 = slot_w[t * 2 + 1];
    const float* r0 = eout + ((size_t)e0 * T_ + p0) * H_;
    const float* r1 = eout + ((size_t)e1 * T_ + p1) * H_;
    const float* hd = hidden + (size_t)t * H_;
    const float* sh = shout + (size_t)t * H_;
    float* op = out + (size_t)t * H_;
    for (int i = threadIdx.x; i < H_; i += 256)
        op[i] = hd[i] + sh[i] + w0 * r0[i] + w1 * r1[i];
}

// ---------------- launch ----------------
static void conv(const float* src, bf16* h, bf16* l, int n) {
    int blocks = (n / 8 + 255) / 256;
    if (blocks > 2048) blocks = 2048;
    conv_kernel<<<blocks, 256>>>(src, h, l, n);
}

extern "C" void kernel_launch(void* const* d_in, const int* in_sizes,
                              int n_in, void* d_out, int out_size) {
    const float* hs  = (const float*)d_in[0];
    const float* ln1 = (const float*)d_in[1];
    const float* ln2 = (const float*)d_in[2];
    const float* wq  = (const float*)d_in[3];
    const float* wk  = (const float*)d_in[4];
    const float* wv  = (const float*)d_in[5];
    const float* wo  = (const float*)d_in[6];
    const float* rw  = (const float*)d_in[7];
    const float* eg  = (const float*)d_in[8];
    const float* eu  = (const float*)d_in[9];
    const float* ed  = (const float*)d_in[10];
    const float* sg  = (const float*)d_in[11];
    const float* su  = (const float*)d_in[12];
    const float* sd  = (const float*)d_in[13];
    float* out = (float*)d_out;

    float *qkv, *hidden, *xn2f, *shg, *shu, *shout, *mg, *mu, *eout;
    float *slot_w;
    int *cnt, *list, *slot_e, *slot_p;
    bf16 *xn1h, *xn1l, *attnh, *attnl, *xn2h, *xn2l;
    bf16 *shah, *shal, *mah, *mal;
    bf16 *qph, *qpl, *kph, *kpl, *vph, *vpl;
    bf16 *wqkvh, *wqkvl, *woh, *wol;
    bf16 *sgh, *sgl, *suh, *sul, *sdh, *sdl;
    bf16 *egh, *egl, *euh, *eul, *edh, *edl;

    cudaGetSymbolAddress((void**)&qkv, g_qkv);
    cudaGetSymbolAddress((void**)&hidden, g_hidden);
    cudaGetSymbolAddress((void**)&xn2f, g_xn2f);
    cudaGetSymbolAddress((void**)&shg, g_shg);
    cudaGetSymbolAddress((void**)&shu, g_shu);
    cudaGetSymbolAddress((void**)&shout, g_shout);
    cudaGetSymbolAddress((void**)&mg, g_mg);
    cudaGetSymbolAddress((void**)&mu, g_mu);
    cudaGetSymbolAddress((void**)&eout, g_eout);
    cudaGetSymbolAddress((void**)&cnt, g_cnt);
    cudaGetSymbolAddress((void**)&list, g_list);
    cudaGetSymbolAddress((void**)&slot_e, g_slot_e);
    cudaGetSymbolAddress((void**)&slot_p, g_slot_p);
    cudaGetSymbolAddress((void**)&slot_w, g_slot_w);
    cudaGetSymbolAddress((void**)&xn1h, g_xn1h);
    cudaGetSymbolAddress((void**)&xn1l, g_xn1l);
    cudaGetSymbolAddress((void**)&attnh, g_attnh);
    cudaGetSymbolAddress((void**)&attnl, g_attnl);
    cudaGetSymbolAddress((void**)&xn2h, g_xn2h);
    cudaGetSymbolAddress((void**)&xn2l, g_xn2l);
    cudaGetSymbolAddress((void**)&shah, g_shah);
    cudaGetSymbolAddress((void**)&shal, g_shal);
    cudaGetSymbolAddress((void**)&mah, g_mah);
    cudaGetSymbolAddress((void**)&mal, g_mal);
    cudaGetSymbolAddress((void**)&qph, g_qph);
    cudaGetSymbolAddress((void**)&qpl, g_qpl);
    cudaGetSymbolAddress((void**)&kph, g_kph);
    cudaGetSymbolAddress((void**)&kpl, g_kpl);
    cudaGetSymbolAddress((void**)&vph, g_vph);
    cudaGetSymbolAddress((void**)&vpl, g_vpl);
    cudaGetSymbolAddress((void**)&wqkvh, g_wqkvh);
    cudaGetSymbolAddress((void**)&wqkvl, g_wqkvl);
    cudaGetSymbolAddress((void**)&woh, g_woh);
    cudaGetSymbolAddress((void**)&wol, g_wol);
    cudaGetSymbolAddress((void**)&sgh, g_sgh);
    cudaGetSymbolAddress((void**)&sgl, g_sgl);
    cudaGetSymbolAddress((void**)&suh, g_suh);
    cudaGetSymbolAddress((void**)&sul, g_sul);
    cudaGetSymbolAddress((void**)&sdh, g_sdh);
    cudaGetSymbolAddress((void**)&sdl, g_sdl);
    cudaGetSymbolAddress((void**)&egh, g_egh);
    cudaGetSymbolAddress((void**)&egl, g_egl);
    cudaGetSymbolAddress((void**)&euh, g_euh);
    cudaGetSymbolAddress((void**)&eul, g_eul);
    cudaGetSymbolAddress((void**)&edh, g_edh);
    cudaGetSymbolAddress((void**)&edl, g_edl);

    cudaFuncSetAttribute(attn_wmma_kernel,
                         cudaFuncAttributeMaxDynamicSharedMemorySize,
                         ATTN_SMEM2);
    cudaFuncSetAttribute(wmma_gemm_kernel,
                         cudaFuncAttributeMaxDynamicSharedMemorySize,
                         GEMM_SMEM);

    // Launch 1: fused qkv weight split
    {
        int n = H_ * QKVN_;
        int blocks = (n / 4 + 255) / 256;
        if (blocks > 2048) blocks = 2048;
        qkvsplit_kernel<<<blocks, 256>>>(wq, wk, wv, wqkvh, wqkvl);
    }
    // Launch 2: ln1
    rmsnorm_pair_kernel<<<T_, 256>>>(hs, ln1, xn1h, xn1l, (float*)0);
    // Launch 3: wo split
    conv(wo, woh, wol, NH_ * HD_ * H_);
    // Launch 4: fused QKV GEMM  (global launch #6 -> profiled by ncu -s 5)
    wmma_gemm_kernel<<<dim3(QKVN_ / 128, 32, 1), 256, GEMM_SMEM>>>(
        xn1h, xn1l, 0, wqkvh, wqkvl, 0, qkv, 0, (const float*)0,
        T_, QKVN_, H_, (const int*)0, (const int*)0);

    // remaining weight splits
    conv(sg, sgh, sgl, H_ * I_);
    conv(su, suh, sul, H_ * I_);
    conv(sd, sdh, sdl, I_ * H_);
    conv(eg, egh, egl, E_ * H_ * I_);
    conv(eu, euh, eul, E_ * H_ * I_);
    conv(ed, edh, edl, E_ * I_ * H_);

    // RoPE (q scaled) / k / v-split from the fused qkv buffer
    rope_pair_kernel<<<(T_ * NH_ * 64 + 255) / 256, 256>>>(
        qkv, QKVN_, 0, qph, qpl, NH_, 0.08838834764831845f);
    rope_pair_kernel<<<(T_ * NKV_ * 64 + 255) / 256, 256>>>(
        qkv, QKVN_, NH_ * HD_, kph, kpl, NKV_, 1.0f);
    {
        int n = T_ * NKV_ * HD_;
        int blocks = (n / 4 + 255) / 256;
        if (blocks > 2048) blocks = 2048;
        conv_sr_kernel<<<blocks, 256>>>(
            qkv, QKVN_, NH_ * HD_ + NKV_ * HD_, T_, NKV_ * HD_, vph, vpl);
    }

    // attention
    attn_wmma_kernel<<<dim3(S_ / 64, NH_, B_), 256, ATTN_SMEM2>>>(
        qph, qpl, kph, kpl, vph, vpl, attnh, attnl);
    // o-proj + residual
    wmma_gemm_kernel<<<dim3(16, 32, 1), 256, GEMM_SMEM>>>(
        attnh, attnl, 0, woh, wol, 0, hidden, 0, hs,
        T_, H_, NH_ * HD_, (const int*)0, (const int*)0);
    // ln2
    rmsnorm_pair_kernel<<<T_, 256>>>(hidden, ln2, xn2h, xn2l, xn2f);
    // shared expert
    wmma_gemm_kernel<<<dim3(8, 32, 1), 256, GEMM_SMEM>>>(
        xn2h, xn2l, 0, sgh, sgl, 0, shg, 0, (const float*)0,
        T_, I_, H_, (const int*)0, (const int*)0);
    wmma_gemm_kernel<<<dim3(8, 32, 1), 256, GEMM_SMEM>>>(
        xn2h, xn2l, 0, suh, sul, 0, shu, 0, (const float*)0,
        T_, I_, H_, (const int*)0, (const int*)0);
    silumul_kernel<<<dim3(T_ * I_ / 1024, 1), 256>>>(
        shg, shu, shah, shal, (const int*)0);
    wmma_gemm_kernel<<<dim3(16, 32, 1), 256, GEMM_SMEM>>>(
        shah, shal, 0, sdh, sdl, 0, shout, 0, (const float*)0,
        T_, H_, I_, (const int*)0, (const int*)0);
    // router + scatter
    zero_cnt_kernel<<<1, 32>>>(cnt);
    router_kernel<<<T_ / 8, 256>>>(xn2f, rw, cnt, list, slot_e, slot_p,
                                   slot_w);
    // routed experts
    wmma_gemm_kernel<<<dim3(8, 32, E_), 256, GEMM_SMEM>>>(
        xn2h, xn2l, 0, egh, egl, (size_t)H_ * I_, mg, (size_t)T_ * I_,
        (const float*)0, T_, I_, H_, cnt, list);
    wmma_gemm_kernel<<<dim3(8, 32, E_), 256, GEMM_SMEM>>>(
        xn2h, xn2l, 0, euh, eul, (size_t)H_ * I_, mu, (size_t)T_ * I_,
        (const float*)0, T_, I_, H_, cnt, list);
    silumul_kernel<<<dim3(T_ * I_ / 1024, E_), 256>>>(mg, mu, mah, mal, cnt);
    wmma_gemm_kernel<<<dim3(16, 32, E_), 256, GEMM_SMEM>>>(
        mah, mal, (size_t)T_ * I_, edh, edl, (size_t)I_ * H_, eout,
        (size_t)T_ * H_, (const float*)0, T_, H_, I_, cnt, (const int*)0);
    // combine
    combine_kernel<<<T_, 256>>>(hidden, shout, eout, slot_e, slot_p,
                                slot_w, out);
}

// round 16
// speedup vs baseline: 1.0783x; 1.0783x over previous
#include <cuda_runtime.h>
#include <cuda_bf16.h>
#include <cuda_pipeline.h>
#include <mma.h>
#include <math.h>

using namespace nvcuda;
typedef __nv_bfloat16 bf16;

// ---------------- problem constants ----------------
constexpr int B_  = 2;
constexpr int S_  = 2048;
constexpr int H_  = 2048;
constexpr int NH_ = 16;
constexpr int NKV_= 4;
constexpr int HD_ = 128;
constexpr int T_  = B_ * S_;
constexpr int E_  = 8;
constexpr int I_  = 1024;
constexpr int I2_ = 2 * I_;                          // 2048
constexpr int QKVN_ = NH_ * HD_ + 2 * NKV_ * HD_;    // 3072
constexpr float EPS_ = 1e-5f;
constexpr float THETA_ = 500000.0f;

// ---------------- scratch (device globals) ----------------
__device__ float g_qkv[T_ * QKVN_];
__device__ float g_hidden[T_ * H_];
__device__ float g_xn2f[T_ * H_];
__device__ float g_shgu[T_ * I2_];
__device__ float g_shout[T_ * H_];
__device__ float g_mgu[(size_t)E_ * T_ * I2_];
__device__ float g_eout[(size_t)E_ * T_ * H_];

__device__ bf16 g_xn1h[T_ * H_];
__device__ bf16 g_xn1l[T_ * H_];
__device__ bf16 g_attnh[T_ * NH_ * HD_];
__device__ bf16 g_attnl[T_ * NH_ * HD_];
__device__ bf16 g_xn2h[T_ * H_];
__device__ bf16 g_xn2l[T_ * H_];
__device__ bf16 g_shah[T_ * I_];
__device__ bf16 g_shal[T_ * I_];
__device__ bf16 g_mah[(size_t)E_ * T_ * I_];
__device__ bf16 g_mal[(size_t)E_ * T_ * I_];

// attention bf16 pair operands
__device__ bf16 g_qph[T_ * NH_ * HD_];
__device__ bf16 g_qpl[T_ * NH_ * HD_];
__device__ bf16 g_kph[T_ * NKV_ * HD_];
__device__ bf16 g_kpl[T_ * NKV_ * HD_];
__device__ bf16 g_vph[T_ * NKV_ * HD_];
__device__ bf16 g_vpl[T_ * NKV_ * HD_];

// weights (bf16 hi/lo)
__device__ bf16 g_wqkvh[H_ * QKVN_];
__device__ bf16 g_wqkvl[H_ * QKVN_];
__device__ bf16 g_woh[NH_ * HD_ * H_];
__device__ bf16 g_wol[NH_ * HD_ * H_];
__device__ bf16 g_wsguh[H_ * I2_];
__device__ bf16 g_wsgul[H_ * I2_];
__device__ bf16 g_sdh[I_ * H_];
__device__ bf16 g_sdl[I_ * H_];
__device__ bf16 g_weguh[(size_t)E_ * H_ * I2_];
__device__ bf16 g_wegul[(size_t)E_ * H_ * I2_];
__device__ bf16 g_edh[(size_t)E_ * I_ * H_];
__device__ bf16 g_edl[(size_t)E_ * I_ * H_];

__device__ int   g_cnt[E_];
__device__ int   g_list[E_ * T_];
__device__ int   g_slot_e[T_ * 2];
__device__ int   g_slot_p[T_ * 2];
__device__ float g_slot_w[T_ * 2];

// ---------------- helpers ----------------
__device__ __forceinline__ void split4(float4 v, bf16* hp, bf16* lp) {
    bf16 h0 = __float2bfloat16(v.x);
    bf16 h1 = __float2bfloat16(v.y);
    bf16 h2 = __float2bfloat16(v.z);
    bf16 h3 = __float2bfloat16(v.w);
    __nv_bfloat162* H2 = (__nv_bfloat162*)hp;
    __nv_bfloat162* L2 = (__nv_bfloat162*)lp;
    H2[0] = __halves2bfloat162(h0, h1);
    H2[1] = __halves2bfloat162(h2, h3);
    L2[0] = __halves2bfloat162(
        __float2bfloat16(v.x - __bfloat162float(h0)),
        __float2bfloat16(v.y - __bfloat162float(h1)));
    L2[1] = __halves2bfloat162(
        __float2bfloat16(v.z - __bfloat162float(h2)),
        __float2bfloat16(v.w - __bfloat162float(h3)));
}

// ---------------- fp32 -> bf16 hi/lo split (grid-stride, 8/iter) ----------
__global__ void conv_kernel(const float* __restrict__ src,
                            bf16* __restrict__ hi,
                            bf16* __restrict__ lo, int n) {
    int stride = gridDim.x * blockDim.x;
    for (int t = blockIdx.x * blockDim.x + threadIdx.x; t * 8 < n;
         t += stride) {
        int i = t * 8;
        float4 v0 = *(const float4*)(src + i);
        float4 v1 = *(const float4*)(src + i + 4);
        split4(v0, hi + i, lo + i);
        split4(v1, hi + i + 4, lo + i + 4);
    }
}

// fused qkv weight split: wq[H,2048] | wk[H,512] | wv[H,512] -> [H,3072] pair
__global__ void qkvsplit_kernel(const float* __restrict__ wq,
                                const float* __restrict__ wk,
                                const float* __restrict__ wv,
                                bf16* __restrict__ hi,
                                bf16* __restrict__ lo) {
    constexpr int NQ = NH_ * HD_;
    constexpr int NKVD = NKV_ * HD_;
    int n = H_ * QKVN_;
    int stride = gridDim.x * blockDim.x;
    for (int t = blockIdx.x * blockDim.x + threadIdx.x; t * 4 < n;
         t += stride) {
        int i = t * 4;
        int r = i / QKVN_;
        int c = i % QKVN_;
        float4 v;
        if (c < NQ) {
            v = *(const float4*)(wq + (size_t)r * NQ + c);
        } else if (c < NQ + NKVD) {
            v = *(const float4*)(wk + (size_t)r * NKVD + (c - NQ));
        } else {
            v = *(const float4*)(wv + (size_t)r * NKVD + (c - NQ - NKVD));
        }
        split4(v, hi + i, lo + i);
    }
}

// concat2 split: rows x (I_|I_) from A,Bs (each [rows, I_] packed) -> pair
__global__ void concat2_split_kernel(const float* __restrict__ A,
                                     const float* __restrict__ Bs,
                                     int rows,
                                     bf16* __restrict__ hi,
                                     bf16* __restrict__ lo) {
    size_t n = (size_t)rows * I2_;
    size_t stride = (size_t)gridDim.x * blockDim.x;
    for (size_t t = blockIdx.x * blockDim.x + threadIdx.x; t * 4 < n;
         t += stride) {
        size_t i = t * 4;
        size_t r = i / I2_;
        int c = (int)(i % I2_);
        float4 v;
        if (c < I_) {
            v = *(const float4*)(A + r * I_ + c);
        } else {
            v = *(const float4*)(Bs + r * I_ + (c - I_));
        }
        split4(v, hi + i, lo + i);
    }
}

// strided-READ split: src at [r*srcStride+srcOff+c] -> packed dst [rows, cols]
__global__ void conv_sr_kernel(const float* __restrict__ src,
                               int srcStride, int srcOff,
                               int rows, int cols,
                               bf16* __restrict__ hi,
                               bf16* __restrict__ lo) {
    int n = rows * cols;
    int stride = gridDim.x * blockDim.x;
    for (int t = blockIdx.x * blockDim.x + threadIdx.x; t * 4 < n;
         t += stride) {
        int i = t * 4;
        int r = i / cols;
        int c = i % cols;
        float4 v = *(const float4*)(src + (size_t)r * srcStride + srcOff + c);
        split4(v, hi + i, lo + i);
    }
}

// ---------------- RMSNorm -> bf16 pair (+ optional fp32 copy) ----------------
__global__ void rmsnorm_pair_kernel(const float* __restrict__ in,
                                    const float* __restrict__ w,
                                    bf16* __restrict__ oh,
                                    bf16* __restrict__ ol,
                                    float* __restrict__ of) {
    int t = blockIdx.x;
    const float* x = in + (size_t)t * H_;
    float ss = 0.f;
    for (int i = threadIdx.x; i < H_; i += 256) {
        float vv = x[i];
        ss += vv * vv;
    }
    __shared__ float red[256];
    red[threadIdx.x] = ss;
    __syncthreads();
    for (int s2 = 128; s2 > 0; s2 >>= 1) {
        if (threadIdx.x < s2) red[threadIdx.x] += red[threadIdx.x + s2];
        __syncthreads();
    }
    float rs = rsqrtf(red[0] / (float)H_ + EPS_);
    size_t base = (size_t)t * H_;
    for (int i = threadIdx.x; i < H_; i += 256) {
        float y = w[i] * x[i] * rs;
        bf16 h = __float2bfloat16(y);
        oh[base + i] = h;
        ol[base + i] = __float2bfloat16(y - __bfloat162float(h));
        if (of) of[base + i] = y;
    }
}

// ============================================================================
// padding banner
// ----------------------------------------------------------------------------
// Inline PTX asm string literals get mangled by the submission transport, so
// this file uses only C++ APIs for tensor-core and async-copy work. This
// banner also keeps the byte region around line ~250 inside comments.
//
// Round 16: round 15 falsified the occupancy theory for the GEMM -- with
// 2-stage smem + __launch_bounds__(256,2), achieved occupancy stayed at 23%
// and the kernel got slightly SLOWER (651 -> 707 us, tensor 38.8 -> 35.8).
// Three GEMM theories (DRAM-bound, L2-bound, occupancy-bound) are now dead;
// the stall structure is intra-CTA (tile-boundary syncs, LDSM->HMMA chains)
// and fixing it requires a structural rewrite, not a knob. So this round:
//  (a) GEMM fully reverted to the proven round-13 shape (3-stage pipeline,
//      plain __launch_bounds__(256)) that backed the 4182 us best;
//  (b) the measured-good fusion pattern (QKV fusion: -50 us) is applied to
//      the remaining gate/up pairs: shared expert sg|su -> one [H,2048]
//      weight and ONE N=2048 GEMM; routed eg|eu -> one [E,H,2048] weight
//      and ONE batched N=2048 GEMM. silumul reads gate at cols [0,I) and
//      up at cols [I,2I) of the fused activation rows and writes the packed
//      [.,I) bf16 pair consumed by the down projections (unchanged).
// The fused QKV GEMM stays at launch #4 so the ncu slot keeps tracking it.
//
// Numerics (bf16x3 split, unchanged): x ~= hi + lo, hi = bf16(x),
// lo = bf16(x - hi); A x B ~= Ah*Bh + Ah*Bl + Al*Bh with fp32 accumulators.
// Layer relative error ~1.2e-5, threshold 1e-3.
// ============================================================================

constexpr int GLDA = 40;
constexpr int GLDB = 136;
constexpr int ATILE = 128 * GLDA;
constexpr int BTILE = 32 * GLDB;
constexpr int STAGE_ELEMS = 2 * ATILE + 2 * BTILE;
constexpr int NSTAGE = 3;
constexpr int GEMM_SMEM = NSTAGE * STAGE_ELEMS * 2;

__global__ void __launch_bounds__(256)
wmma_gemm_kernel(const bf16* __restrict__ Ah, const bf16* __restrict__ Al,
                 size_t sA,
                 const bf16* __restrict__ Bh, const bf16* __restrict__ Bl,
                 size_t sB,
                 float* __restrict__ C, size_t sC,
                 const float* __restrict__ addend,
                 int M, int N, int K,
                 const int* __restrict__ counts,
                 const int* __restrict__ lists) {
    extern __shared__ __align__(16) bf16 smg[];

    int z = blockIdx.z;
    int Mz = M;
    if (counts) {
        int c = counts[z];
        if (c < Mz) Mz = c;
    }
    int m0 = blockIdx.y * 128;
    if (m0 >= Mz) return;
    int n0 = blockIdx.x * 128;
    Ah += (size_t)z * sA;
    Al += (size_t)z * sA;
    Bh += (size_t)z * sB;
    Bl += (size_t)z * sB;
    C += (size_t)z * sC;
    if (addend) addend += (size_t)z * sC;
    const int* lst = lists ? (lists + (size_t)z * T_) : (const int*)0;

    int tid = threadIdx.x;
    int w = tid >> 5;
    int wm = w >> 1;
    int wn = w & 1;

    int aRow = tid >> 1;
    int aCol = (tid & 1) << 4;
    int bRow = tid >> 3;
    int bCol = (tid & 7) << 4;

    wmma::fragment<wmma::accumulator, 16, 16, 16, float> acc[2][4];
    for (int mi = 0; mi < 2; mi++)
        for (int nj = 0; nj < 4; nj++)
            wmma::fill_fragment(acc[mi][nj], 0.0f);

    int nk = K / 32;

    auto load_stage = [&](int k0, int st) {
        bf16* sAh = smg + st * STAGE_ELEMS;
        bf16* sAl = sAh + ATILE;
        bf16* sBh = sAl + ATILE;
        bf16* sBl = sBh + BTILE;
        int grow = m0 + aRow;
        bf16* dh = sAh + aRow * GLDA + aCol;
        bf16* dl = sAl + aRow * GLDA + aCol;
        if (grow < Mz) {
            int arow = lst ? lst[grow] : grow;
            size_t off = (size_t)arow * K + k0 + aCol;
            __pipeline_memcpy_async(dh, Ah + off, 16);
            __pipeline_memcpy_async(dh + 8, Ah + off + 8, 16);
            __pipeline_memcpy_async(dl, Al + off, 16);
            __pipeline_memcpy_async(dl + 8, Al + off + 8, 16);
        } else {
            int4 zz = make_int4(0, 0, 0, 0);
            *(int4*)dh = zz;
            *(int4*)(dh + 8) = zz;
            *(int4*)dl = zz;
            *(int4*)(dl + 8) = zz;
        }
        size_t boff = (size_t)(k0 + bRow) * N + n0 + bCol;
        bf16* ebh = sBh + bRow * GLDB + bCol;
        bf16* ebl = sBl + bRow * GLDB + bCol;
        __pipeline_memcpy_async(ebh, Bh + boff, 16);
        __pipeline_memcpy_async(ebh + 8, Bh + boff + 8, 16);
        __pipeline_memcpy_async(ebl, Bl + boff, 16);
        __pipeline_memcpy_async(ebl + 8, Bl + boff + 8, 16);
    };

    load_stage(0, 0);
    __pipeline_commit();
    if (nk > 1) {
        load_stage(32, 1);
        __pipeline_commit();
    }

    for (int ki = 0; ki < nk; ki++) {
        if (ki + 2 < nk) {
            load_stage((ki + 2) * 32, (ki + 2) % NSTAGE);
            __pipeline_commit();
            __pipeline_wait_prior(2);
        } else if (ki + 1 < nk) {
            __pipeline_wait_prior(1);
        } else {
            __pipeline_wait_prior(0);
        }
        __syncthreads();

        int st = ki % NSTAGE;
        bf16* sAh = smg + st * STAGE_ELEMS;
        bf16* sAl = sAh + ATILE;
        bf16* sBh = sAl + ATILE;
        bf16* sBl = sBh + BTILE;

        for (int kb = 0; kb < 32; kb += 16) {
            wmma::fragment<wmma::matrix_a, 16, 16, 16, bf16,
                           wmma::row_major> fah[2], fal[2];
            for (int mi = 0; mi < 2; mi++) {
                const bf16* pa = sAh + (wm * 32 + mi * 16) * GLDA + kb;
                wmma::load_matrix_sync(fah[mi], pa, GLDA);
                const bf16* pl = sAl + (wm * 32 + mi * 16) * GLDA + kb;
                wmma::load_matrix_sync(fal[mi], pl, GLDA);
            }
            wmma::fragment<wmma::matrix_b, 16, 16, 16, bf16,
                           wmma::row_major> fbh[4], fbl[4];
            for (int nj = 0; nj < 4; nj++) {
                const bf16* pb = sBh + kb * GLDB + wn * 64 + nj * 16;
                wmma::load_matrix_sync(fbh[nj], pb, GLDB);
                const bf16* pl = sBl + kb * GLDB + wn * 64 + nj * 16;
                wmma::load_matrix_sync(fbl[nj], pl, GLDB);
            }
            for (int mi = 0; mi < 2; mi++) {
                for (int nj = 0; nj < 4; nj++) {
                    wmma::mma_sync(acc[mi][nj], fah[mi], fbh[nj],
                                   acc[mi][nj]);
                    wmma::mma_sync(acc[mi][nj], fah[mi], fbl[nj],
                                   acc[mi][nj]);
                    wmma::mma_sync(acc[mi][nj], fal[mi], fbh[nj],
                                   acc[mi][nj]);
                }
            }
        }
        __syncthreads();
    }

    for (int mi = 0; mi < 2; mi++) {
        for (int nj = 0; nj < 4; nj++) {
            int row = m0 + wm * 32 + mi * 16;
            int col = n0 + wn * 64 + nj * 16;
            float* cp = C + (size_t)row * N + col;
            if (addend) {
                wmma::fragment<wmma::accumulator, 16, 16, 16, float> fc;
                const float* ap = addend + (size_t)row * N + col;
                wmma::load_matrix_sync(fc, ap, N, wmma::mem_row_major);
                for (int e = 0; e < fc.num_elements; e++)
                    acc[mi][nj].x[e] += fc.x[e];
            }
            wmma::store_matrix_sync(cp, acc[mi][nj], N,
                                    wmma::mem_row_major);
        }
    }
}

// ---------------- RoPE from strided src -> packed bf16 hi/lo pair ----------
__global__ void rope_pair_kernel(const float* __restrict__ src,
                                 int srcStride, int srcOff,
                                 bf16* __restrict__ oh,
                                 bf16* __restrict__ ol,
                                 int nheads, float mul) {
    int idx = blockIdx.x * blockDim.x + threadIdx.x;
    int total = T_ * nheads * (HD_ / 2);
    if (idx >= total) return;
    int d = idx & 63;
    int rest = idx >> 6;
    int h = rest % nheads;
    int t = rest / nheads;
    int pos = t % S_;
    float inv = powf(THETA_, -(float)d / 64.0f);
    float ang = (float)pos * inv;
    float c = cosf(ang);
    float sn = sinf(ang);
    size_t sbase = (size_t)t * srcStride + srcOff + h * HD_;
    size_t dbase = (size_t)t * nheads * HD_ + h * HD_;
    float x1 = src[sbase + d];
    float x2 = src[sbase + d + 64];
    float y1 = (x1 * c - x2 * sn) * mul;
    float y2 = (x2 * c + x1 * sn) * mul;
    bf16 h1 = __float2bfloat16(y1);
    bf16 h2 = __float2bfloat16(y2);
    oh[dbase + d] = h1;
    oh[dbase + d + 64] = h2;
    ol[dbase + d] = __float2bfloat16(y1 - __bfloat162float(h1));
    ol[dbase + d + 64] = __float2bfloat16(y2 - __bfloat162float(h2));
}

// ---------------- wmma flash attention (O in registers) ----------------
constexpr int AQLD = 136;
constexpr int ASLD = 72;
constexpr int ATTN_SMEM2 =
    6 * 64 * AQLD * 2 +
    64 * ASLD * 4 +
    2 * 64 * ASLD * 2 +
    64 * AQLD * 4 +
    3 * 64 * 4;

__global__ void __launch_bounds__(256, 1)
attn_wmma_kernel(const bf16* __restrict__ qh, const bf16* __restrict__ ql,
                 const bf16* __restrict__ kh, const bf16* __restrict__ kl,
                 const bf16* __restrict__ vh, const bf16* __restrict__ vl,
                 bf16* __restrict__ oh, bf16* __restrict__ ol) {
    extern __shared__ char smraw[];
    bf16* Qh = (bf16*)smraw;
    bf16* Ql = Qh + 64 * AQLD;
    bf16* Kh = Ql + 64 * AQLD;
    bf16* Kl = Kh + 64 * AQLD;
    bf16* Vh = Kl + 64 * AQLD;
    bf16* Vl = Vh + 64 * AQLD;
    float* Ss = (float*)(Vl + 64 * AQLD);
    bf16* Ph = (bf16*)(Ss + 64 * ASLD);
    bf16* Pl = Ph + 64 * ASLD;
    float* Os = (float*)(Pl + 64 * ASLD);
    float* Mr = Os + 64 * AQLD;
    float* Lr = Mr + 64;
    float* Ar = Lr + 64;

    int qt = (int)(gridDim.x - 1) - (int)blockIdx.x;
    int h = blockIdx.y;
    int b = blockIdx.z;
    int hk = h >> 2;
    int tid = threadIdx.x;
    int w = tid >> 5;
    int lane = tid & 31;
    int wm = w >> 1;
    int wn = w & 1;
    int accRow0 = wm * 16 + (lane >> 2);
    int accRow1 = accRow0 + 8;

    for (int i = tid; i < 64 * 16; i += 256) {
        int row = i >> 4;
        int c8 = (i & 15) << 3;
        int token = b * S_ + qt * 64 + row;
        size_t off = (size_t)token * (NH_ * HD_) + h * HD_ + c8;
        *(int4*)(Qh + row * AQLD + c8) = *(const int4*)(qh + off);
        *(int4*)(Ql + row * AQLD + c8) = *(const int4*)(ql + off);
    }
    if (tid < 64) {
        Mr[tid] = -1e30f;
        Lr[tid] = 0.f;
    }

    wmma::fragment<wmma::accumulator, 16, 16, 16, float> oacc[4];
    for (int nj = 0; nj < 4; nj++)
        wmma::fill_fragment(oacc[nj], 0.0f);
    __syncthreads();

    for (int kt = 0; kt <= qt; kt++) {
        for (int i = tid; i < 64 * 16; i += 256) {
            int row = i >> 4;
            int c8 = (i & 15) << 3;
            int token = b * S_ + kt * 64 + row;
            size_t off = (size_t)token * (NKV_ * HD_) + hk * HD_ + c8;
            *(int4*)(Kh + row * AQLD + c8) = *(const int4*)(kh + off);
            *(int4*)(Kl + row * AQLD + c8) = *(const int4*)(kl + off);
            *(int4*)(Vh + row * AQLD + c8) = *(const int4*)(vh + off);
            *(int4*)(Vl + row * AQLD + c8) = *(const int4*)(vl + off);
        }
        __syncthreads();

        {
            wmma::fragment<wmma::accumulator, 16, 16, 16, float> sacc[2];
            wmma::fill_fragment(sacc[0], 0.0f);
            wmma::fill_fragment(sacc[1], 0.0f);
            for (int ks = 0; ks < 8; ks++) {
                wmma::fragment<wmma::matrix_a, 16, 16, 16, bf16,
                               wmma::row_major> fqh, fql;
                const bf16* pq = Qh + (wm * 16) * AQLD + ks * 16;
                wmma::load_matrix_sync(fqh, pq, AQLD);
                const bf16* pq2 = Ql + (wm * 16) * AQLD + ks * 16;
                wmma::load_matrix_sync(fql, pq2, AQLD);
                for (int nj = 0; nj < 2; nj++) {
                    wmma::fragment<wmma::matrix_b, 16, 16, 16, bf16,
                                   wmma::col_major> fkh, fkl;
                    const bf16* pk =
                        Kh + (wn * 32 + nj * 16) * AQLD + ks * 16;
                    wmma::load_matrix_sync(fkh, pk, AQLD);
                    const bf16* pk2 =
                        Kl + (wn * 32 + nj * 16) * AQLD + ks * 16;
                    wmma::load_matrix_sync(fkl, pk2, AQLD);
                    wmma::mma_sync(sacc[nj], fqh, fkh, sacc[nj]);
                    wmma::mma_sync(sacc[nj], fqh, fkl, sacc[nj]);
                    wmma::mma_sync(sacc[nj], fql, fkh, sacc[nj]);
                }
            }
            for (int nj = 0; nj < 2; nj++) {
                float* ps = Ss + (wm * 16) * ASLD + wn * 32 + nj * 16;
                wmma::store_matrix_sync(ps, sacc[nj], ASLD,
                                        wmma::mem_row_major);
            }
        }
        __syncthreads();

        {
            int r = tid >> 2;
            int sub = tid & 3;
            int c0 = sub * 16;
            bool diag = (kt == qt);
            float mOld = Mr[r];
            float mx = mOld;
            for (int c = c0; c < c0 + 16; c++) {
                float val = Ss[r * ASLD + c];
                if (diag && c > r) val = -1e30f;
                mx = fmaxf(mx, val);
            }
            mx = fmaxf(mx, __shfl_xor_sync(0xffffffffu, mx, 1));
            mx = fmaxf(mx, __shfl_xor_sync(0xffffffffu, mx, 2));
            float sum = 0.f;
            for (int c = c0; c < c0 + 16; c++) {
                float val = Ss[r * ASLD + c];
                if (diag && c > r) val = -1e30f;
                float p = __expf(val - mx);
                bf16 phv = __float2bfloat16(p);
                Ph[r * ASLD + c] = phv;
                Pl[r * ASLD + c] =
                    __float2bfloat16(p - __bfloat162float(phv));
                sum += p;
            }
            sum += __shfl_xor_sync(0xffffffffu, sum, 1);
            sum += __shfl_xor_sync(0xffffffffu, sum, 2);
            if (sub == 0) {
                float alpha = __expf(mOld - mx);
                Lr[r] = Lr[r] * alpha + sum;
                Mr[r] = mx;
                Ar[r] = alpha;
            }
        }
        __syncthreads();

        {
            float a0 = Ar[accRow0];
            float a1 = Ar[accRow1];
            for (int nj = 0; nj < 4; nj++) {
                for (int e = 0; e < 8; e++) {
                    oacc[nj].x[e] *= (e & 2) ? a1 : a0;
                }
            }
        }

        for (int ks = 0; ks < 4; ks++) {
            wmma::fragment<wmma::matrix_a, 16, 16, 16, bf16,
                           wmma::row_major> fph, fpl;
            const bf16* pp = Ph + (wm * 16) * ASLD + ks * 16;
            wmma::load_matrix_sync(fph, pp, ASLD);
            const bf16* pp2 = Pl + (wm * 16) * ASLD + ks * 16;
            wmma::load_matrix_sync(fpl, pp2, ASLD);
            for (int nj = 0; nj < 4; nj++) {
                wmma::fragment<wmma::matrix_b, 16, 16, 16, bf16,
                               wmma::row_major> fvh, fvl;
                const bf16* pv =
                    Vh + (ks * 16) * AQLD + wn * 64 + nj * 16;
                wmma::load_matrix_sync(fvh, pv, AQLD);
                const bf16* pv2 =
                    Vl + (ks * 16) * AQLD + wn * 64 + nj * 16;
                wmma::load_matrix_sync(fvl, pv2, AQLD);
                wmma::mma_sync(oacc[nj], fph, fvh, oacc[nj]);
                wmma::mma_sync(oacc[nj], fph, fvl, oacc[nj]);
                wmma::mma_sync(oacc[nj], fpl, fvh, oacc[nj]);
            }
        }
        __syncthreads();
    }

    {
        float i0 = 1.0f / Lr[accRow0];
        float i1 = 1.0f / Lr[accRow1];
        for (int nj = 0; nj < 4; nj++) {
            for (int e = 0; e < 8; e++) {
                oacc[nj].x[e] *= (e & 2) ? i1 : i0;
            }
            float* po = Os + (wm * 16) * AQLD + wn * 64 + nj * 16;
            wmma::store_matrix_sync(po, oacc[nj], AQLD,
                                    wmma::mem_row_major);
        }
    }
    __syncthreads();

    for (int i = tid; i < 64 * 32; i += 256) {
        int r = i >> 5;
        int c4 = (i & 31) << 2;
        int token = b * S_ + qt * 64 + r;
        size_t off = (size_t)token * (NH_ * HD_) + h * HD_ + c4;
        for (int j = 0; j < 4; j++) {
            float val = Os[r * AQLD + c4 + j];
            bf16 hv = __float2bfloat16(val);
            oh[off + j] = hv;
            ol[off + j] = __float2bfloat16(val - __bfloat162float(hv));
        }
    }
}

// ---------------- SiLU(g)*u from fused [rows, 2I] rows -> bf16 pair -------
__global__ void silumul_f_kernel(const float* __restrict__ gu,
                                 bf16* __restrict__ oh,
                                 bf16* __restrict__ ol,
                                 const int* __restrict__ counts) {
    int z = blockIdx.y;
    int M = counts ? counts[z] : T_;
    int idx = (blockIdx.x * 256 + threadIdx.x) * 4;
    if (idx >= T_ * I_) return;
    int row = idx / I_;
    if (row >= M) return;
    int col = idx % I_;
    size_t sbase = ((size_t)z * T_ + row) * I2_;
    float4 gv = *(const float4*)(gu + sbase + col);
    float4 uv = *(const float4*)(gu + sbase + I_ + col);
    float a0 = gv.x / (1.f + __expf(-gv.x)) * uv.x;
    float a1 = gv.y / (1.f + __expf(-gv.y)) * uv.y;
    float a2 = gv.z / (1.f + __expf(-gv.z)) * uv.z;
    float a3 = gv.w / (1.f + __expf(-gv.w)) * uv.w;
    float4 av = make_float4(a0, a1, a2, a3);
    size_t dbase = (size_t)z * T_ * I_ + idx;
    split4(av, oh + dbase, ol + dbase);
}

// ---------------- router ----------------
__global__ void zero_cnt_kernel(int* cnt) {
    if (threadIdx.x < E_) cnt[threadIdx.x] = 0;
}

__global__ void router_kernel(const float* __restrict__ xn2,
                              const float* __restrict__ rw,
                              int* __restrict__ cnt, int* __restrict__ list,
                              int* __restrict__ slot_e,
                              int* __restrict__ slot_p,
                              float* __restrict__ slot_w) {
    int t = blockIdx.x * 8 + (threadIdx.x >> 5);
    int lane = threadIdx.x & 31;
    if (t >= T_) return;
    const float* x = xn2 + (size_t)t * H_;
    float s[E_];
    for (int e = 0; e < E_; e++) s[e] = 0.f;
    for (int i = lane; i < H_; i += 32) {
        float xv = x[i];
        for (int e = 0; e < E_; e++) s[e] += xv * rw[i * E_ + e];
    }
    for (int off = 16; off > 0; off >>= 1)
        for (int e = 0; e < E_; e++)
            s[e] += __shfl_down_sync(0xffffffffu, s[e], off);
    if (lane == 0) {
        float se[E_];
        for (int e = 0; e < E_; e++) se[e] = fmaxf(s[e], 0.f);
        int i1 = 0;
        float v1 = se[0];
        for (int e = 1; e < E_; e++) {
            if (se[e] > v1) { v1 = se[e]; i1 = e; }
        }
        int i2 = -1;
        float v2 = -1.f;
        for (int e = 0; e < E_; e++) {
            if (e != i1 && se[e] > v2) { v2 = se[e]; i2 = e; }
        }
        float denom = v1 + v2 + 1e-6f;
        float w1 = v1 / denom;
        float w2 = v2 / denom;
        int p1 = atomicAdd(&cnt[i1], 1);
        list[i1 * T_ + p1] = t;
        int p2 = atomicAdd(&cnt[i2], 1);
        list[i2 * T_ + p2] = t;
        slot_e[t * 2] = i1;
        slot_p[t * 2] = p1;
        slot_w[t * 2] = w1;
        slot_e[t * 2 + 1] = i2;
        slot_p[t * 2 + 1] = p2;
        slot_w[t * 2 + 1] = w2;
    }
}

// ---------------- final combine ----------------
__global__ void combine_kernel(const float* __restrict__ hidden,
                               const float* __restrict__ shout,
                               const float* __restrict__ eout,
                               const int* __restrict__ slot_e,
                               const int* __restrict__ slot_p,
                               const float* __restrict__ slot_w,
                               float* __restrict__ out) {
    int t = blockIdx.x;
    int e0 = slot_e[t * 2];
    int e1 = slot_e[t * 2 + 1];
    int p0 = slot_p[t * 2];
    int p1 = slot_p[t * 2 + 1];
    float w0 = slot_w[t * 2];
    float w1 = slot_w[t * 2 + 1];
    const float* r0 = eout + ((size_t)e0 * T_ + p0) * H_;
    const float* r1 = eout + ((size_t)e1 * T_ + p1) * H_;
    const float* hd = hidden + (size_t)t * H_;
    const float* sh = shout + (size_t)t * H_;
    float* op = out + (size_t)t * H_;
    for (int i = threadIdx.x; i < H_; i += 256)
        op[i] = hd[i] + sh[i] + w0 * r0[i] + w1 * r1[i];
}

// ---------------- launch ----------------
static void conv(const float* src, bf16* h, bf16* l, int n) {
    int blocks = (n / 8 + 255) / 256;
    if (blocks > 2048) blocks = 2048;
    conv_kernel<<<blocks, 256>>>(src, h, l, n);
}

extern "C" void kernel_launch(void* const* d_in, const int* in_sizes,
                              int n_in, void* d_out, int out_size) {
    const float* hs  = (const float*)d_in[0];
    const float* ln1 = (const float*)d_in[1];
    const float* ln2 = (const float*)d_in[2];
    const float* wq  = (const float*)d_in[3];
    const float* wk  = (const float*)d_in[4];
    const float* wv  = (const float*)d_in[5];
    const float* wo  = (const float*)d_in[6];
    const float* rw  = (const float*)d_in[7];
    const float* eg  = (const float*)d_in[8];
    const float* eu  = (const float*)d_in[9];
    const float* ed  = (const float*)d_in[10];
    const float* sg  = (const float*)d_in[11];
    const float* su  = (const float*)d_in[12];
    const float* sd  = (const float*)d_in[13];
    float* out = (float*)d_out;

    float *qkv, *hidden, *xn2f, *shgu, *shout, *mgu, *eout;
    float *slot_w;
    int *cnt, *list, *slot_e, *slot_p;
    bf16 *xn1h, *xn1l, *attnh, *attnl, *xn2h, *xn2l;
    bf16 *shah, *shal, *mah, *mal;
    bf16 *qph, *qpl, *kph, *kpl, *vph, *vpl;
    bf16 *wqkvh, *wqkvl, *woh, *wol;
    bf16 *wsguh, *wsgul, *sdh, *sdl;
    bf16 *weguh, *wegul, *edh, *edl;

    cudaGetSymbolAddress((void**)&qkv, g_qkv);
    cudaGetSymbolAddress((void**)&hidden, g_hidden);
    cudaGetSymbolAddress((void**)&xn2f, g_xn2f);
    cudaGetSymbolAddress((void**)&shgu, g_shgu);
    cudaGetSymbolAddress((void**)&shout, g_shout);
    cudaGetSymbolAddress((void**)&mgu, g_mgu);
    cudaGetSymbolAddress((void**)&eout, g_eout);
    cudaGetSymbolAddress((void**)&cnt, g_cnt);
    cudaGetSymbolAddress((void**)&list, g_list);
    cudaGetSymbolAddress((void**)&slot_e, g_slot_e);
    cudaGetSymbolAddress((void**)&slot_p, g_slot_p);
    cudaGetSymbolAddress((void**)&slot_w, g_slot_w);
    cudaGetSymbolAddress((void**)&xn1h, g_xn1h);
    cudaGetSymbolAddress((void**)&xn1l, g_xn1l);
    cudaGetSymbolAddress((void**)&attnh, g_attnh);
    cudaGetSymbolAddress((void**)&attnl, g_attnl);
    cudaGetSymbolAddress((void**)&xn2h, g_xn2h);
    cudaGetSymbolAddress((void**)&xn2l, g_xn2l);
    cudaGetSymbolAddress((void**)&shah, g_shah);
    cudaGetSymbolAddress((void**)&shal, g_shal);
    cudaGetSymbolAddress((void**)&mah, g_mah);
    cudaGetSymbolAddress((void**)&mal, g_mal);
    cudaGetSymbolAddress((void**)&qph, g_qph);
    cudaGetSymbolAddress((void**)&qpl, g_qpl);
    cudaGetSymbolAddress((void**)&kph, g_kph);
    cudaGetSymbolAddress((void**)&kpl, g_kpl);
    cudaGetSymbolAddress((void**)&vph, g_vph);
    cudaGetSymbolAddress((void**)&vpl, g_vpl);
    cudaGetSymbolAddress((void**)&wqkvh, g_wqkvh);
    cudaGetSymbolAddress((void**)&wqkvl, g_wqkvl);
    cudaGetSymbolAddress((void**)&woh, g_woh);
    cudaGetSymbolAddress((void**)&wol, g_wol);
    cudaGetSymbolAddress((void**)&wsguh, g_wsguh);
    cudaGetSymbolAddress((void**)&wsgul, g_wsgul);
    cudaGetSymbolAddress((void**)&sdh, g_sdh);
    cudaGetSymbolAddress((void**)&sdl, g_sdl);
    cudaGetSymbolAddress((void**)&weguh, g_weguh);
    cudaGetSymbolAddress((void**)&wegul, g_wegul);
    cudaGetSymbolAddress((void**)&edh, g_edh);
    cudaGetSymbolAddress((void**)&edl, g_edl);

    cudaFuncSetAttribute(attn_wmma_kernel,
                         cudaFuncAttributeMaxDynamicSharedMemorySize,
                         ATTN_SMEM2);
    cudaFuncSetAttribute(wmma_gemm_kernel,
                         cudaFuncAttributeMaxDynamicSharedMemorySize,
                         GEMM_SMEM);

    // Launch 1: fused qkv weight split
    {
        int n = H_ * QKVN_;
        int blocks = (n / 4 + 255) / 256;
        if (blocks > 2048) blocks = 2048;
        qkvsplit_kernel<<<blocks, 256>>>(wq, wk, wv, wqkvh, wqkvl);
    }
    // Launch 2: ln1
    rmsnorm_pair_kernel<<<T_, 256>>>(hs, ln1, xn1h, xn1l, (float*)0);
    // Launch 3: wo split
    conv(wo, woh, wol, NH_ * HD_ * H_);
    // Launch 4: fused QKV GEMM (global launch #6 -> profiled by ncu -s 5)
    wmma_gemm_kernel<<<dim3(QKVN_ / 128, 32, 1), 256, GEMM_SMEM>>>(
        xn1h, xn1l, 0, wqkvh, wqkvl, 0, qkv, 0, (const float*)0,
        T_, QKVN_, H_, (const int*)0, (const int*)0);

    // remaining weight splits: fused gate|up concat for shared + routed
    {
        int blocks = 2048;
        concat2_split_kernel<<<blocks, 256>>>(sg, su, H_, wsguh, wsgul);
        concat2_split_kernel<<<blocks, 256>>>(eg, eu, E_ * H_,
                                              weguh, wegul);
    }
    conv(sd, sdh, sdl, I_ * H_);
    conv(ed, edh, edl, E_ * I_ * H_);

    // RoPE (q scaled) / k / v-split from the fused qkv buffer
    rope_pair_kernel<<<(T_ * NH_ * 64 + 255) / 256, 256>>>(
        qkv, QKVN_, 0, qph, qpl, NH_, 0.08838834764831845f);
    rope_pair_kernel<<<(T_ * NKV_ * 64 + 255) / 256, 256>>>(
        qkv, QKVN_, NH_ * HD_, kph, kpl, NKV_, 1.0f);
    {
        int n = T_ * NKV_ * HD_;
        int blocks = (n / 4 + 255) / 256;
        if (blocks > 2048) blocks = 2048;
        conv_sr_kernel<<<blocks, 256>>>(
            qkv, QKVN_, NH_ * HD_ + NKV_ * HD_, T_, NKV_ * HD_, vph, vpl);
    }

    // attention
    attn_wmma_kernel<<<dim3(S_ / 64, NH_, B_), 256, ATTN_SMEM2>>>(
        qph, qpl, kph, kpl, vph, vpl, attnh, attnl);
    // o-proj + residual
    wmma_gemm_kernel<<<dim3(16, 32, 1), 256, GEMM_SMEM>>>(
        attnh, attnl, 0, woh, wol, 0, hidden, 0, hs,
        T_, H_, NH_ * HD_, (const int*)0, (const int*)0);
    // ln2
    rmsnorm_pair_kernel<<<T_, 256>>>(hidden, ln2, xn2h, xn2l, xn2f);
    // shared expert: fused gate|up GEMM (N=2048), silu-mul, down
    wmma_gemm_kernel<<<dim3(I2_ / 128, 32, 1), 256, GEMM_SMEM>>>(
        xn2h, xn2l, 0, wsguh, wsgul, 0, shgu, 0, (const float*)0,
        T_, I2_, H_, (const int*)0, (const int*)0);
    silumul_f_kernel<<<dim3(T_ * I_ / 1024, 1), 256>>>(
        shgu, shah, shal, (const int*)0);
    wmma_gemm_kernel<<<dim3(16, 32, 1), 256, GEMM_SMEM>>>(
        shah, shal, 0, sdh, sdl, 0, shout, 0, (const float*)0,
        T_, H_, I_, (const int*)0, (const int*)0);
    // router + scatter
    zero_cnt_kernel<<<1, 32>>>(cnt);
    router_kernel<<<T_ / 8, 256>>>(xn2f, rw, cnt, list, slot_e, slot_p,
                                   slot_w);
    // routed experts: fused gate|up batched GEMM, silu-mul, batched down
    wmma_gemm_kernel<<<dim3(I2_ / 128, 32, E_), 256, GEMM_SMEM>>>(
        xn2h, xn2l, 0, weguh, wegul, (size_t)H_ * I2_, mgu,
        (size_t)T_ * I2_, (const float*)0, T_, I2_, H_, cnt, list);
    silumul_f_kernel<<<dim3(T_ * I_ / 1024, E_), 256>>>(
        mgu, mah, mal, cnt);
    wmma_gemm_kernel<<<dim3(16, 32, E_), 256, GEMM_SMEM>>>(
        mah, mal, (size_t)T_ * I_, edh, edl, (size_t)I_ * H_, eout,
        (size_t)T_ * H_, (const float*)0, T_, H_, I_, cnt, (const int*)0);
    // combine
    combine_kernel<<<T_, 256>>>(hidden, shout, eout, slot_e, slot_p,
                                slot_w, out);
}

// round 17
// speedup vs baseline: 1.0836x; 1.0048x over previous
#include <cuda_runtime.h>
#include <cuda_bf16.h>
#include <cuda_pipeline.h>
#include <mma.h>
#include <math.h>

using namespace nvcuda;
typedef __nv_bfloat16 bf16;

// ---------------- problem constants ----------------
constexpr int B_  = 2;
constexpr int S_  = 2048;
constexpr int H_  = 2048;
constexpr int NH_ = 16;
constexpr int NKV_= 4;
constexpr int HD_ = 128;
constexpr int T_  = B_ * S_;
constexpr int E_  = 8;
constexpr int I_  = 1024;
constexpr int I2_ = 2 * I_;                          // 2048
constexpr int QKVN_ = NH_ * HD_ + 2 * NKV_ * HD_;    // 3072
constexpr float EPS_ = 1e-5f;
constexpr float THETA_ = 500000.0f;

// ---------------- scratch (device globals) ----------------
__device__ float g_qkv[T_ * QKVN_];
__device__ float g_hidden[T_ * H_];
__device__ float g_xn2f[T_ * H_];
__device__ float g_shgu[T_ * I2_];
__device__ float g_shout[T_ * H_];
__device__ float g_mgu[(size_t)E_ * T_ * I2_];
__device__ float g_eout[(size_t)E_ * T_ * H_];

__device__ bf16 g_xn1h[T_ * H_];
__device__ bf16 g_xn1l[T_ * H_];
__device__ bf16 g_attnh[T_ * NH_ * HD_];
__device__ bf16 g_attnl[T_ * NH_ * HD_];
__device__ bf16 g_xn2h[T_ * H_];
__device__ bf16 g_xn2l[T_ * H_];
__device__ bf16 g_shah[T_ * I_];
__device__ bf16 g_shal[T_ * I_];
__device__ bf16 g_mah[(size_t)E_ * T_ * I_];
__device__ bf16 g_mal[(size_t)E_ * T_ * I_];

// attention bf16 pair operands
__device__ bf16 g_qph[T_ * NH_ * HD_];
__device__ bf16 g_qpl[T_ * NH_ * HD_];
__device__ bf16 g_kph[T_ * NKV_ * HD_];
__device__ bf16 g_kpl[T_ * NKV_ * HD_];
__device__ bf16 g_vph[T_ * NKV_ * HD_];
__device__ bf16 g_vpl[T_ * NKV_ * HD_];

// weights (bf16 hi/lo)
__device__ bf16 g_wqkvh[H_ * QKVN_];
__device__ bf16 g_wqkvl[H_ * QKVN_];
__device__ bf16 g_woh[NH_ * HD_ * H_];
__device__ bf16 g_wol[NH_ * HD_ * H_];
__device__ bf16 g_wsguh[H_ * I2_];
__device__ bf16 g_wsgul[H_ * I2_];
__device__ bf16 g_sdh[I_ * H_];
__device__ bf16 g_sdl[I_ * H_];
__device__ bf16 g_weguh[(size_t)E_ * H_ * I2_];
__device__ bf16 g_wegul[(size_t)E_ * H_ * I2_];
__device__ bf16 g_edh[(size_t)E_ * I_ * H_];
__device__ bf16 g_edl[(size_t)E_ * I_ * H_];

__device__ int   g_cnt[E_];
__device__ int   g_list[E_ * T_];
__device__ int   g_slot_e[T_ * 2];
__device__ int   g_slot_p[T_ * 2];
__device__ float g_slot_w[T_ * 2];

// ---------------- helpers ----------------
__device__ __forceinline__ void split4(float4 v, bf16* hp, bf16* lp) {
    bf16 h0 = __float2bfloat16(v.x);
    bf16 h1 = __float2bfloat16(v.y);
    bf16 h2 = __float2bfloat16(v.z);
    bf16 h3 = __float2bfloat16(v.w);
    __nv_bfloat162* H2 = (__nv_bfloat162*)hp;
    __nv_bfloat162* L2 = (__nv_bfloat162*)lp;
    H2[0] = __halves2bfloat162(h0, h1);
    H2[1] = __halves2bfloat162(h2, h3);
    L2[0] = __halves2bfloat162(
        __float2bfloat16(v.x - __bfloat162float(h0)),
        __float2bfloat16(v.y - __bfloat162float(h1)));
    L2[1] = __halves2bfloat162(
        __float2bfloat16(v.z - __bfloat162float(h2)),
        __float2bfloat16(v.w - __bfloat162float(h3)));
}

// ---------------- fp32 -> bf16 hi/lo split (grid-stride, 8/iter) ----------
__global__ void conv_kernel(const float* __restrict__ src,
                            bf16* __restrict__ hi,
                            bf16* __restrict__ lo, int n) {
    int stride = gridDim.x * blockDim.x;
    for (int t = blockIdx.x * blockDim.x + threadIdx.x; t * 8 < n;
         t += stride) {
        int i = t * 8;
        float4 v0 = *(const float4*)(src + i);
        float4 v1 = *(const float4*)(src + i + 4);
        split4(v0, hi + i, lo + i);
        split4(v1, hi + i + 4, lo + i + 4);
    }
}

// fused qkv weight split: wq[H,2048] | wk[H,512] | wv[H,512] -> [H,3072] pair
__global__ void qkvsplit_kernel(const float* __restrict__ wq,
                                const float* __restrict__ wk,
                                const float* __restrict__ wv,
                                bf16* __restrict__ hi,
                                bf16* __restrict__ lo) {
    constexpr int NQ = NH_ * HD_;
    constexpr int NKVD = NKV_ * HD_;
    int n = H_ * QKVN_;
    int stride = gridDim.x * blockDim.x;
    for (int t = blockIdx.x * blockDim.x + threadIdx.x; t * 4 < n;
         t += stride) {
        int i = t * 4;
        int r = i / QKVN_;
        int c = i % QKVN_;
        float4 v;
        if (c < NQ) {
            v = *(const float4*)(wq + (size_t)r * NQ + c);
        } else if (c < NQ + NKVD) {
            v = *(const float4*)(wk + (size_t)r * NKVD + (c - NQ));
        } else {
            v = *(const float4*)(wv + (size_t)r * NKVD + (c - NQ - NKVD));
        }
        split4(v, hi + i, lo + i);
    }
}

// concat2 split: rows x (I_|I_) from A,Bs (each [rows, I_] packed) -> pair
__global__ void concat2_split_kernel(const float* __restrict__ A,
                                     const float* __restrict__ Bs,
                                     int rows,
                                     bf16* __restrict__ hi,
                                     bf16* __restrict__ lo) {
    size_t n = (size_t)rows * I2_;
    size_t stride = (size_t)gridDim.x * blockDim.x;
    for (size_t t = blockIdx.x * blockDim.x + threadIdx.x; t * 4 < n;
         t += stride) {
        size_t i = t * 4;
        size_t r = i / I2_;
        int c = (int)(i % I2_);
        float4 v;
        if (c < I_) {
            v = *(const float4*)(A + r * I_ + c);
        } else {
            v = *(const float4*)(Bs + r * I_ + (c - I_));
        }
        split4(v, hi + i, lo + i);
    }
}

// strided-READ split: src at [r*srcStride+srcOff+c] -> packed dst [rows, cols]
__global__ void conv_sr_kernel(const float* __restrict__ src,
                               int srcStride, int srcOff,
                               int rows, int cols,
                               bf16* __restrict__ hi,
                               bf16* __restrict__ lo) {
    int n = rows * cols;
    int stride = gridDim.x * blockDim.x;
    for (int t = blockIdx.x * blockDim.x + threadIdx.x; t * 4 < n;
         t += stride) {
        int i = t * 4;
        int r = i / cols;
        int c = i % cols;
        float4 v = *(const float4*)(src + (size_t)r * srcStride + srcOff + c);
        split4(v, hi + i, lo + i);
    }
}

// ---------------- RMSNorm -> bf16 pair (+ optional fp32 copy) ----------------
__global__ void rmsnorm_pair_kernel(const float* __restrict__ in,
                                    const float* __restrict__ w,
                                    bf16* __restrict__ oh,
                                    bf16* __restrict__ ol,
                                    float* __restrict__ of) {
    int t = blockIdx.x;
    const float* x = in + (size_t)t * H_;
    float ss = 0.f;
    for (int i = threadIdx.x; i < H_; i += 256) {
        float vv = x[i];
        ss += vv * vv;
    }
    __shared__ float red[256];
    red[threadIdx.x] = ss;
    __syncthreads();
    for (int s2 = 128; s2 > 0; s2 >>= 1) {
        if (threadIdx.x < s2) red[threadIdx.x] += red[threadIdx.x + s2];
        __syncthreads();
    }
    float rs = rsqrtf(red[0] / (float)H_ + EPS_);
    size_t base = (size_t)t * H_;
    for (int i = threadIdx.x; i < H_; i += 256) {
        float y = w[i] * x[i] * rs;
        bf16 h = __float2bfloat16(y);
        oh[base + i] = h;
        ol[base + i] = __float2bfloat16(y - __bfloat162float(h));
        if (of) of[base + i] = y;
    }
}

// ============================================================================
// padding banner
// ----------------------------------------------------------------------------
// Inline PTX asm string literals get mangled by the submission transport, so
// this file uses only C++ APIs for tensor-core and async-copy work. This
// banner also keeps the byte region around line ~250 inside comments.
//
// Round 17: round 16 confirmed the GEMM revert (650.7us / tensor 38.7% --
// byte-identical to round 14) and banked the gate/up fusions (-40us).
// The GEMM is frozen: DRAM-, L2- and occupancy-theories are all falsified
// and its ~237 TF/s is pinned by intra-CTA wmma dependency structure.
// This round scales the ATTENTION tile: BQ 64 -> 128 with 512 threads
// (16 warps). Per-warp shapes are identical to the proven kernel (16x32
// S-tile, 16x64 O-tile, oacc[4], softmax 4 threads/row); only the warp-row
// index wm now ranges over 8. K/V tiles stay 64 rows and now serve twice
// the query rows, halving K/V global traffic and amortizing the per-step
// sync/softmax overhead over 2x work. Shared memory: Q pair 69.6KB + KV
// pairs 69.6KB + S 36.9KB + P pair 36.9KB + M/L/A 1.5KB = 214.5KB (under
// the 227KB cap); the final O staging reuses the Q region (exactly 69632B,
// Q is dead after the KV loop). The causal mask is computed from global
// indices (kt*64 + c > qt*128 + r); fully-masked rows are safe because
// their running max is finite from earlier steps (alpha = 1, sum = 0).
//
// Numerics (bf16x3 split, unchanged): x ~= hi + lo, hi = bf16(x),
// lo = bf16(x - hi); A x B ~= Ah*Bh + Ah*Bl + Al*Bh with fp32 accumulators.
// Layer relative error ~1.2e-5, threshold 1e-3.
// ============================================================================

constexpr int GLDA = 40;
constexpr int GLDB = 136;
constexpr int ATILE = 128 * GLDA;
constexpr int BTILE = 32 * GLDB;
constexpr int STAGE_ELEMS = 2 * ATILE + 2 * BTILE;
constexpr int NSTAGE = 3;
constexpr int GEMM_SMEM = NSTAGE * STAGE_ELEMS * 2;

__global__ void __launch_bounds__(256)
wmma_gemm_kernel(const bf16* __restrict__ Ah, const bf16* __restrict__ Al,
                 size_t sA,
                 const bf16* __restrict__ Bh, const bf16* __restrict__ Bl,
                 size_t sB,
                 float* __restrict__ C, size_t sC,
                 const float* __restrict__ addend,
                 int M, int N, int K,
                 const int* __restrict__ counts,
                 const int* __restrict__ lists) {
    extern __shared__ __align__(16) bf16 smg[];

    int z = blockIdx.z;
    int Mz = M;
    if (counts) {
        int c = counts[z];
        if (c < Mz) Mz = c;
    }
    int m0 = blockIdx.y * 128;
    if (m0 >= Mz) return;
    int n0 = blockIdx.x * 128;
    Ah += (size_t)z * sA;
    Al += (size_t)z * sA;
    Bh += (size_t)z * sB;
    Bl += (size_t)z * sB;
    C += (size_t)z * sC;
    if (addend) addend += (size_t)z * sC;
    const int* lst = lists ? (lists + (size_t)z * T_) : (const int*)0;

    int tid = threadIdx.x;
    int w = tid >> 5;
    int wm = w >> 1;
    int wn = w & 1;

    int aRow = tid >> 1;
    int aCol = (tid & 1) << 4;
    int bRow = tid >> 3;
    int bCol = (tid & 7) << 4;

    wmma::fragment<wmma::accumulator, 16, 16, 16, float> acc[2][4];
    for (int mi = 0; mi < 2; mi++)
        for (int nj = 0; nj < 4; nj++)
            wmma::fill_fragment(acc[mi][nj], 0.0f);

    int nk = K / 32;

    auto load_stage = [&](int k0, int st) {
        bf16* sAh = smg + st * STAGE_ELEMS;
        bf16* sAl = sAh + ATILE;
        bf16* sBh = sAl + ATILE;
        bf16* sBl = sBh + BTILE;
        int grow = m0 + aRow;
        bf16* dh = sAh + aRow * GLDA + aCol;
        bf16* dl = sAl + aRow * GLDA + aCol;
        if (grow < Mz) {
            int arow = lst ? lst[grow] : grow;
            size_t off = (size_t)arow * K + k0 + aCol;
            __pipeline_memcpy_async(dh, Ah + off, 16);
            __pipeline_memcpy_async(dh + 8, Ah + off + 8, 16);
            __pipeline_memcpy_async(dl, Al + off, 16);
            __pipeline_memcpy_async(dl + 8, Al + off + 8, 16);
        } else {
            int4 zz = make_int4(0, 0, 0, 0);
            *(int4*)dh = zz;
            *(int4*)(dh + 8) = zz;
            *(int4*)dl = zz;
            *(int4*)(dl + 8) = zz;
        }
        size_t boff = (size_t)(k0 + bRow) * N + n0 + bCol;
        bf16* ebh = sBh + bRow * GLDB + bCol;
        bf16* ebl = sBl + bRow * GLDB + bCol;
        __pipeline_memcpy_async(ebh, Bh + boff, 16);
        __pipeline_memcpy_async(ebh + 8, Bh + boff + 8, 16);
        __pipeline_memcpy_async(ebl, Bl + boff, 16);
        __pipeline_memcpy_async(ebl + 8, Bl + boff + 8, 16);
    };

    load_stage(0, 0);
    __pipeline_commit();
    if (nk > 1) {
        load_stage(32, 1);
        __pipeline_commit();
    }

    for (int ki = 0; ki < nk; ki++) {
        if (ki + 2 < nk) {
            load_stage((ki + 2) * 32, (ki + 2) % NSTAGE);
            __pipeline_commit();
            __pipeline_wait_prior(2);
        } else if (ki + 1 < nk) {
            __pipeline_wait_prior(1);
        } else {
            __pipeline_wait_prior(0);
        }
        __syncthreads();

        int st = ki % NSTAGE;
        bf16* sAh = smg + st * STAGE_ELEMS;
        bf16* sAl = sAh + ATILE;
        bf16* sBh = sAl + ATILE;
        bf16* sBl = sBh + BTILE;

        for (int kb = 0; kb < 32; kb += 16) {
            wmma::fragment<wmma::matrix_a, 16, 16, 16, bf16,
                           wmma::row_major> fah[2], fal[2];
            for (int mi = 0; mi < 2; mi++) {
                const bf16* pa = sAh + (wm * 32 + mi * 16) * GLDA + kb;
                wmma::load_matrix_sync(fah[mi], pa, GLDA);
                const bf16* pl = sAl + (wm * 32 + mi * 16) * GLDA + kb;
                wmma::load_matrix_sync(fal[mi], pl, GLDA);
            }
            wmma::fragment<wmma::matrix_b, 16, 16, 16, bf16,
                           wmma::row_major> fbh[4], fbl[4];
            for (int nj = 0; nj < 4; nj++) {
                const bf16* pb = sBh + kb * GLDB + wn * 64 + nj * 16;
                wmma::load_matrix_sync(fbh[nj], pb, GLDB);
                const bf16* pl = sBl + kb * GLDB + wn * 64 + nj * 16;
                wmma::load_matrix_sync(fbl[nj], pl, GLDB);
            }
            for (int mi = 0; mi < 2; mi++) {
                for (int nj = 0; nj < 4; nj++) {
                    wmma::mma_sync(acc[mi][nj], fah[mi], fbh[nj],
                                   acc[mi][nj]);
                    wmma::mma_sync(acc[mi][nj], fah[mi], fbl[nj],
                                   acc[mi][nj]);
                    wmma::mma_sync(acc[mi][nj], fal[mi], fbh[nj],
                                   acc[mi][nj]);
                }
            }
        }
        __syncthreads();
    }

    for (int mi = 0; mi < 2; mi++) {
        for (int nj = 0; nj < 4; nj++) {
            int row = m0 + wm * 32 + mi * 16;
            int col = n0 + wn * 64 + nj * 16;
            float* cp = C + (size_t)row * N + col;
            if (addend) {
                wmma::fragment<wmma::accumulator, 16, 16, 16, float> fc;
                const float* ap = addend + (size_t)row * N + col;
                wmma::load_matrix_sync(fc, ap, N, wmma::mem_row_major);
                for (int e = 0; e < fc.num_elements; e++)
                    acc[mi][nj].x[e] += fc.x[e];
            }
            wmma::store_matrix_sync(cp, acc[mi][nj], N,
                                    wmma::mem_row_major);
        }
    }
}

// ---------------- RoPE from strided src -> packed bf16 hi/lo pair ----------
__global__ void rope_pair_kernel(const float* __restrict__ src,
                                 int srcStride, int srcOff,
                                 bf16* __restrict__ oh,
                                 bf16* __restrict__ ol,
                                 int nheads, float mul) {
    int idx = blockIdx.x * blockDim.x + threadIdx.x;
    int total = T_ * nheads * (HD_ / 2);
    if (idx >= total) return;
    int d = idx & 63;
    int rest = idx >> 6;
    int h = rest % nheads;
    int t = rest / nheads;
    int pos = t % S_;
    float inv = powf(THETA_, -(float)d / 64.0f);
    float ang = (float)pos * inv;
    float c = cosf(ang);
    float sn = sinf(ang);
    size_t sbase = (size_t)t * srcStride + srcOff + h * HD_;
    size_t dbase = (size_t)t * nheads * HD_ + h * HD_;
    float x1 = src[sbase + d];
    float x2 = src[sbase + d + 64];
    float y1 = (x1 * c - x2 * sn) * mul;
    float y2 = (x2 * c + x1 * sn) * mul;
    bf16 h1 = __float2bfloat16(y1);
    bf16 h2 = __float2bfloat16(y2);
    oh[dbase + d] = h1;
    oh[dbase + d + 64] = h2;
    ol[dbase + d] = __float2bfloat16(y1 - __bfloat162float(h1));
    ol[dbase + d + 64] = __float2bfloat16(y2 - __bfloat162float(h2));
}

// ---------------- wmma flash attention, BQ=128, 512 threads ----------------
constexpr int AQLD = 136;
constexpr int ASLD = 72;
constexpr int ATTN_SMEM3 =
    2 * 128 * AQLD * 2 +           // Qh Ql (bf16, 128 rows)
    4 * 64 * AQLD * 2 +            // Kh Kl Vh Vl (bf16, 64 rows)
    128 * ASLD * 4 +               // S (fp32, 128 rows)
    2 * 128 * ASLD * 2 +           // Ph Pl (bf16, 128 rows)
    3 * 128 * 4;                   // M L A rows
// final O staging reuses the Q region (128*AQLD*4 = 69632 = Q pair bytes)

__global__ void __launch_bounds__(512, 1)
attn_wmma_kernel(const bf16* __restrict__ qh, const bf16* __restrict__ ql,
                 const bf16* __restrict__ kh, const bf16* __restrict__ kl,
                 const bf16* __restrict__ vh, const bf16* __restrict__ vl,
                 bf16* __restrict__ oh, bf16* __restrict__ ol) {
    extern __shared__ char smraw[];
    bf16* Qh = (bf16*)smraw;
    bf16* Ql = Qh + 128 * AQLD;
    bf16* Kh = Ql + 128 * AQLD;
    bf16* Kl = Kh + 64 * AQLD;
    bf16* Vh = Kl + 64 * AQLD;
    bf16* Vl = Vh + 64 * AQLD;
    float* Ss = (float*)(Vl + 64 * AQLD);
    bf16* Ph = (bf16*)(Ss + 128 * ASLD);
    bf16* Pl = Ph + 128 * ASLD;
    float* Mr = (float*)(Pl + 128 * ASLD);
    float* Lr = Mr + 128;
    float* Ar = Lr + 128;
    float* Os = (float*)smraw;      // reuse Q region after KV loop

    int qt = (int)(gridDim.x - 1) - (int)blockIdx.x;  // heavy CTAs first
    int h = blockIdx.y;
    int b = blockIdx.z;
    int hk = h >> 2;
    int tid = threadIdx.x;
    int w = tid >> 5;
    int lane = tid & 31;
    int wm = w >> 1;     // 0..7 (16-row slice of 128)
    int wn = w & 1;      // 0..1
    int accRow0 = wm * 16 + (lane >> 2);
    int accRow1 = accRow0 + 8;

    // load Q tile (128 x 128, hi+lo), init M/L
    for (int i = tid; i < 128 * 16; i += 512) {
        int row = i >> 4;
        int c8 = (i & 15) << 3;
        int token = b * S_ + qt * 128 + row;
        size_t off = (size_t)token * (NH_ * HD_) + h * HD_ + c8;
        *(int4*)(Qh + row * AQLD + c8) = *(const int4*)(qh + off);
        *(int4*)(Ql + row * AQLD + c8) = *(const int4*)(ql + off);
    }
    if (tid < 128) {
        Mr[tid] = -1e30f;
        Lr[tid] = 0.f;
    }

    wmma::fragment<wmma::accumulator, 16, 16, 16, float> oacc[4];
    for (int nj = 0; nj < 4; nj++)
        wmma::fill_fragment(oacc[nj], 0.0f);
    __syncthreads();

    int ktmax = 2 * qt + 1;
    for (int kt = 0; kt <= ktmax; kt++) {
        // load K/V tiles (64 rows, hi+lo)
        for (int i = tid; i < 64 * 16; i += 512) {
            int row = i >> 4;
            int c8 = (i & 15) << 3;
            int token = b * S_ + kt * 64 + row;
            size_t off = (size_t)token * (NKV_ * HD_) + hk * HD_ + c8;
            *(int4*)(Kh + row * AQLD + c8) = *(const int4*)(kh + off);
            *(int4*)(Kl + row * AQLD + c8) = *(const int4*)(kl + off);
            *(int4*)(Vh + row * AQLD + c8) = *(const int4*)(vh + off);
            *(int4*)(Vl + row * AQLD + c8) = *(const int4*)(vl + off);
        }
        __syncthreads();

        // S = Q K^T (3-term). warp tile 16x32 of the 128x64 score tile.
        {
            wmma::fragment<wmma::accumulator, 16, 16, 16, float> sacc[2];
            wmma::fill_fragment(sacc[0], 0.0f);
            wmma::fill_fragment(sacc[1], 0.0f);
            for (int ks = 0; ks < 8; ks++) {
                wmma::fragment<wmma::matrix_a, 16, 16, 16, bf16,
                               wmma::row_major> fqh, fql;
                const bf16* pq = Qh + (wm * 16) * AQLD + ks * 16;
                wmma::load_matrix_sync(fqh, pq, AQLD);
                const bf16* pq2 = Ql + (wm * 16) * AQLD + ks * 16;
                wmma::load_matrix_sync(fql, pq2, AQLD);
                for (int nj = 0; nj < 2; nj++) {
                    wmma::fragment<wmma::matrix_b, 16, 16, 16, bf16,
                                   wmma::col_major> fkh, fkl;
                    const bf16* pk =
                        Kh + (wn * 32 + nj * 16) * AQLD + ks * 16;
                    wmma::load_matrix_sync(fkh, pk, AQLD);
                    const bf16* pk2 =
                        Kl + (wn * 32 + nj * 16) * AQLD + ks * 16;
                    wmma::load_matrix_sync(fkl, pk2, AQLD);
                    wmma::mma_sync(sacc[nj], fqh, fkh, sacc[nj]);
                    wmma::mma_sync(sacc[nj], fqh, fkl, sacc[nj]);
                    wmma::mma_sync(sacc[nj], fql, fkh, sacc[nj]);
                }
            }
            for (int nj = 0; nj < 2; nj++) {
                float* ps = Ss + (wm * 16) * ASLD + wn * 32 + nj * 16;
                wmma::store_matrix_sync(ps, sacc[nj], ASLD,
                                        wmma::mem_row_major);
            }
        }
        __syncthreads();

        // online softmax: 4 threads per row, 16 columns each; global mask
        {
            int r = tid >> 2;
            int sub = tid & 3;
            int c0 = sub * 16;
            int qrow = qt * 128 + r;
            int kbase = kt * 64;
            float mOld = Mr[r];
            float mx = mOld;
            for (int c = c0; c < c0 + 16; c++) {
                float val = Ss[r * ASLD + c];
                if (kbase + c > qrow) val = -1e30f;
                mx = fmaxf(mx, val);
            }
            mx = fmaxf(mx, __shfl_xor_sync(0xffffffffu, mx, 1));
            mx = fmaxf(mx, __shfl_xor_sync(0xffffffffu, mx, 2));
            float sum = 0.f;
            for (int c = c0; c < c0 + 16; c++) {
                float val = Ss[r * ASLD + c];
                if (kbase + c > qrow) val = -1e30f;
                float p = __expf(val - mx);
                bf16 phv = __float2bfloat16(p);
                Ph[r * ASLD + c] = phv;
                Pl[r * ASLD + c] =
                    __float2bfloat16(p - __bfloat162float(phv));
                sum += p;
            }
            sum += __shfl_xor_sync(0xffffffffu, sum, 1);
            sum += __shfl_xor_sync(0xffffffffu, sum, 2);
            if (sub == 0) {
                float alpha = __expf(mOld - mx);
                Lr[r] = Lr[r] * alpha + sum;
                Mr[r] = mx;
                Ar[r] = alpha;
            }
        }
        __syncthreads();

        // rescale O fragments in registers by per-row alpha
        {
            float a0 = Ar[accRow0];
            float a1 = Ar[accRow1];
            for (int nj = 0; nj < 4; nj++) {
                for (int e = 0; e < 8; e++) {
                    oacc[nj].x[e] *= (e & 2) ? a1 : a0;
                }
            }
        }

        // O += P V (3-term), accumulating in registers. warp tile 16x64.
        for (int ks = 0; ks < 4; ks++) {
            wmma::fragment<wmma::matrix_a, 16, 16, 16, bf16,
                           wmma::row_major> fph, fpl;
            const bf16* pp = Ph + (wm * 16) * ASLD + ks * 16;
            wmma::load_matrix_sync(fph, pp, ASLD);
            const bf16* pp2 = Pl + (wm * 16) * ASLD + ks * 16;
            wmma::load_matrix_sync(fpl, pp2, ASLD);
            for (int nj = 0; nj < 4; nj++) {
                wmma::fragment<wmma::matrix_b, 16, 16, 16, bf16,
                               wmma::row_major> fvh, fvl;
                const bf16* pv =
                    Vh + (ks * 16) * AQLD + wn * 64 + nj * 16;
                wmma::load_matrix_sync(fvh, pv, AQLD);
                const bf16* pv2 =
                    Vl + (ks * 16) * AQLD + wn * 64 + nj * 16;
                wmma::load_matrix_sync(fvl, pv2, AQLD);
                wmma::mma_sync(oacc[nj], fph, fvh, oacc[nj]);
                wmma::mma_sync(oacc[nj], fph, fvl, oacc[nj]);
                wmma::mma_sync(oacc[nj], fpl, fvh, oacc[nj]);
            }
        }
        __syncthreads();
    }

    // normalize in registers, stage through Q-region smem, write bf16 pairs
    {
        float i0 = 1.0f / Lr[accRow0];
        float i1 = 1.0f / Lr[accRow1];
        for (int nj = 0; nj < 4; nj++) {
            for (int e = 0; e < 8; e++) {
                oacc[nj].x[e] *= (e & 2) ? i1 : i0;
            }
        }
    }
    __syncthreads();   // everyone done reading Q before Os overwrites it
    for (int nj = 0; nj < 4; nj++) {
        float* po = Os + (wm * 16) * AQLD + wn * 64 + nj * 16;
        wmma::store_matrix_sync(po, oacc[nj], AQLD, wmma::mem_row_major);
    }
    __syncthreads();

    for (int i = tid; i < 128 * 32; i += 512) {
        int r = i >> 5;
        int c4 = (i & 31) << 2;
        int token = b * S_ + qt * 128 + r;
        size_t off = (size_t)token * (NH_ * HD_) + h * HD_ + c4;
        for (int j = 0; j < 4; j++) {
            float val = Os[r * AQLD + c4 + j];
            bf16 hv = __float2bfloat16(val);
            oh[off + j] = hv;
            ol[off + j] = __float2bfloat16(val - __bfloat162float(hv));
        }
    }
}

// ---------------- SiLU(g)*u from fused [rows, 2I] rows -> bf16 pair -------
__global__ void silumul_f_kernel(const float* __restrict__ gu,
                                 bf16* __restrict__ oh,
                                 bf16* __restrict__ ol,
                                 const int* __restrict__ counts) {
    int z = blockIdx.y;
    int M = counts ? counts[z] : T_;
    int idx = (blockIdx.x * 256 + threadIdx.x) * 4;
    if (idx >= T_ * I_) return;
    int row = idx / I_;
    if (row >= M) return;
    int col = idx % I_;
    size_t sbase = ((size_t)z * T_ + row) * I2_;
    float4 gv = *(const float4*)(gu + sbase + col);
    float4 uv = *(const float4*)(gu + sbase + I_ + col);
    float a0 = gv.x / (1.f + __expf(-gv.x)) * uv.x;
    float a1 = gv.y / (1.f + __expf(-gv.y)) * uv.y;
    float a2 = gv.z / (1.f + __expf(-gv.z)) * uv.z;
    float a3 = gv.w / (1.f + __expf(-gv.w)) * uv.w;
    float4 av = make_float4(a0, a1, a2, a3);
    size_t dbase = (size_t)z * T_ * I_ + idx;
    split4(av, oh + dbase, ol + dbase);
}

// ---------------- router ----------------
__global__ void zero_cnt_kernel(int* cnt) {
    if (threadIdx.x < E_) cnt[threadIdx.x] = 0;
}

__global__ void router_kernel(const float* __restrict__ xn2,
                              const float* __restrict__ rw,
                              int* __restrict__ cnt, int* __restrict__ list,
                              int* __restrict__ slot_e,
                              int* __restrict__ slot_p,
                              float* __restrict__ slot_w) {
    int t = blockIdx.x * 8 + (threadIdx.x >> 5);
    int lane = threadIdx.x & 31;
    if (t >= T_) return;
    const float* x = xn2 + (size_t)t * H_;
    float s[E_];
    for (int e = 0; e < E_; e++) s[e] = 0.f;
    for (int i = lane; i < H_; i += 32) {
        float xv = x[i];
        for (int e = 0; e < E_; e++) s[e] += xv * rw[i * E_ + e];
    }
    for (int off = 16; off > 0; off >>= 1)
        for (int e = 0; e < E_; e++)
            s[e] += __shfl_down_sync(0xffffffffu, s[e], off);
    if (lane == 0) {
        float se[E_];
        for (int e = 0; e < E_; e++) se[e] = fmaxf(s[e], 0.f);
        int i1 = 0;
        float v1 = se[0];
        for (int e = 1; e < E_; e++) {
            if (se[e] > v1) { v1 = se[e]; i1 = e; }
        }
        int i2 = -1;
        float v2 = -1.f;
        for (int e = 0; e < E_; e++) {
            if (e != i1 && se[e] > v2) { v2 = se[e]; i2 = e; }
        }
        float denom = v1 + v2 + 1e-6f;
        float w1 = v1 / denom;
        float w2 = v2 / denom;
        int p1 = atomicAdd(&cnt[i1], 1);
        list[i1 * T_ + p1] = t;
        int p2 = atomicAdd(&cnt[i2], 1);
        list[i2 * T_ + p2] = t;
        slot_e[t * 2] = i1;
        slot_p[t * 2] = p1;
        slot_w[t * 2] = w1;
        slot_e[t * 2 + 1] = i2;
        slot_p[t * 2 + 1] = p2;
        slot_w[t * 2 + 1] = w2;
    }
}

// ---------------- final combine ----------------
__global__ void combine_kernel(const float* __restrict__ hidden,
                               const float* __restrict__ shout,
                               const float* __restrict__ eout,
                               const int* __restrict__ slot_e,
                               const int* __restrict__ slot_p,
                               const float* __restrict__ slot_w,
                               float* __restrict__ out) {
    int t = blockIdx.x;
    int e0 = slot_e[t * 2];
    int e1 = slot_e[t * 2 + 1];
    int p0 = slot_p[t * 2];
    int p1 = slot_p[t * 2 + 1];
    float w0 = slot_w[t * 2];
    float w1 = slot_w[t * 2 + 1];
    const float* r0 = eout + ((size_t)e0 * T_ + p0) * H_;
    const float* r1 = eout + ((size_t)e1 * T_ + p1) * H_;
    const float* hd = hidden + (size_t)t * H_;
    const float* sh = shout + (size_t)t * H_;
    float* op = out + (size_t)t * H_;
    for (int i = threadIdx.x; i < H_; i += 256)
        op[i] = hd[i] + sh[i] + w0 * r0[i] + w1 * r1[i];
}

// ---------------- launch ----------------
static void conv(const float* src, bf16* h, bf16* l, int n) {
    int blocks = (n / 8 + 255) / 256;
    if (blocks > 2048) blocks = 2048;
    conv_kernel<<<blocks, 256>>>(src, h, l, n);
}

extern "C" void kernel_launch(void* const* d_in, const int* in_sizes,
                              int n_in, void* d_out, int out_size) {
    const float* hs  = (const float*)d_in[0];
    const float* ln1 = (const float*)d_in[1];
    const float* ln2 = (const float*)d_in[2];
    const float* wq  = (const float*)d_in[3];
    const float* wk  = (const float*)d_in[4];
    const float* wv  = (const float*)d_in[5];
    const float* wo  = (const float*)d_in[6];
    const float* rw  = (const float*)d_in[7];
    const float* eg  = (const float*)d_in[8];
    const float* eu  = (const float*)d_in[9];
    const float* ed  = (const float*)d_in[10];
    const float* sg  = (const float*)d_in[11];
    const float* su  = (const float*)d_in[12];
    const float* sd  = (const float*)d_in[13];
    float* out = (float*)d_out;

    float *qkv, *hidden, *xn2f, *shgu, *shout, *mgu, *eout;
    float *slot_w;
    int *cnt, *list, *slot_e, *slot_p;
    bf16 *xn1h, *xn1l, *attnh, *attnl, *xn2h, *xn2l;
    bf16 *shah, *shal, *mah, *mal;
    bf16 *qph, *qpl, *kph, *kpl, *vph, *vpl;
    bf16 *wqkvh, *wqkvl, *woh, *wol;
    bf16 *wsguh, *wsgul, *sdh, *sdl;
    bf16 *weguh, *wegul, *edh, *edl;

    cudaGetSymbolAddress((void**)&qkv, g_qkv);
    cudaGetSymbolAddress((void**)&hidden, g_hidden);
    cudaGetSymbolAddress((void**)&xn2f, g_xn2f);
    cudaGetSymbolAddress((void**)&shgu, g_shgu);
    cudaGetSymbolAddress((void**)&shout, g_shout);
    cudaGetSymbolAddress((void**)&mgu, g_mgu);
    cudaGetSymbolAddress((void**)&eout, g_eout);
    cudaGetSymbolAddress((void**)&cnt, g_cnt);
    cudaGetSymbolAddress((void**)&list, g_list);
    cudaGetSymbolAddress((void**)&slot_e, g_slot_e);
    cudaGetSymbolAddress((void**)&slot_p, g_slot_p);
    cudaGetSymbolAddress((void**)&slot_w, g_slot_w);
    cudaGetSymbolAddress((void**)&xn1h, g_xn1h);
    cudaGetSymbolAddress((void**)&xn1l, g_xn1l);
    cudaGetSymbolAddress((void**)&attnh, g_attnh);
    cudaGetSymbolAddress((void**)&attnl, g_attnl);
    cudaGetSymbolAddress((void**)&xn2h, g_xn2h);
    cudaGetSymbolAddress((void**)&xn2l, g_xn2l);
    cudaGetSymbolAddress((void**)&shah, g_shah);
    cudaGetSymbolAddress((void**)&shal, g_shal);
    cudaGetSymbolAddress((void**)&mah, g_mah);
    cudaGetSymbolAddress((void**)&mal, g_mal);
    cudaGetSymbolAddress((void**)&qph, g_qph);
    cudaGetSymbolAddress((void**)&qpl, g_qpl);
    cudaGetSymbolAddress((void**)&kph, g_kph);
    cudaGetSymbolAddress((void**)&kpl, g_kpl);
    cudaGetSymbolAddress((void**)&vph, g_vph);
    cudaGetSymbolAddress((void**)&vpl, g_vpl);
    cudaGetSymbolAddress((void**)&wqkvh, g_wqkvh);
    cudaGetSymbolAddress((void**)&wqkvl, g_wqkvl);
    cudaGetSymbolAddress((void**)&woh, g_woh);
    cudaGetSymbolAddress((void**)&wol, g_wol);
    cudaGetSymbolAddress((void**)&wsguh, g_wsguh);
    cudaGetSymbolAddress((void**)&wsgul, g_wsgul);
    cudaGetSymbolAddress((void**)&sdh, g_sdh);
    cudaGetSymbolAddress((void**)&sdl, g_sdl);
    cudaGetSymbolAddress((void**)&weguh, g_weguh);
    cudaGetSymbolAddress((void**)&wegul, g_wegul);
    cudaGetSymbolAddress((void**)&edh, g_edh);
    cudaGetSymbolAddress((void**)&edl, g_edl);

    cudaFuncSetAttribute(attn_wmma_kernel,
                         cudaFuncAttributeMaxDynamicSharedMemorySize,
                         ATTN_SMEM3);
    cudaFuncSetAttribute(wmma_gemm_kernel,
                         cudaFuncAttributeMaxDynamicSharedMemorySize,
                         GEMM_SMEM);

    // Launch 1: fused qkv weight split
    {
        int n = H_ * QKVN_;
        int blocks = (n / 4 + 255) / 256;
        if (blocks > 2048) blocks = 2048;
        qkvsplit_kernel<<<blocks, 256>>>(wq, wk, wv, wqkvh, wqkvl);
    }
    // Launch 2: ln1
    rmsnorm_pair_kernel<<<T_, 256>>>(hs, ln1, xn1h, xn1l, (float*)0);
    // Launch 3: wo split
    conv(wo, woh, wol, NH_ * HD_ * H_);
    // Launch 4: fused QKV GEMM (global launch #6 -> profiled by ncu -s 5)
    wmma_gemm_kernel<<<dim3(QKVN_ / 128, 32, 1), 256, GEMM_SMEM>>>(
        xn1h, xn1l, 0, wqkvh, wqkvl, 0, qkv, 0, (const float*)0,
        T_, QKVN_, H_, (const int*)0, (const int*)0);

    // remaining weight splits: fused gate|up concat for shared + routed
    {
        int blocks = 2048;
        concat2_split_kernel<<<blocks, 256>>>(sg, su, H_, wsguh, wsgul);
        concat2_split_kernel<<<blocks, 256>>>(eg, eu, E_ * H_,
                                              weguh, wegul);
    }
    conv(sd, sdh, sdl, I_ * H_);
    conv(ed, edh, edl, E_ * I_ * H_);

    // RoPE (q scaled) / k / v-split from the fused qkv buffer
    rope_pair_kernel<<<(T_ * NH_ * 64 + 255) / 256, 256>>>(
        qkv, QKVN_, 0, qph, qpl, NH_, 0.08838834764831845f);
    rope_pair_kernel<<<(T_ * NKV_ * 64 + 255) / 256, 256>>>(
        qkv, QKVN_, NH_ * HD_, kph, kpl, NKV_, 1.0f);
    {
        int n = T_ * NKV_ * HD_;
        int blocks = (n / 4 + 255) / 256;
        if (blocks > 2048) blocks = 2048;
        conv_sr_kernel<<<blocks, 256>>>(
            qkv, QKVN_, NH_ * HD_ + NKV_ * HD_, T_, NKV_ * HD_, vph, vpl);
    }

    // attention (BQ=128, 512 threads)
    attn_wmma_kernel<<<dim3(S_ / 128, NH_, B_), 512, ATTN_SMEM3>>>(
        qph, qpl, kph, kpl, vph, vpl, attnh, attnl);
    // o-proj + residual
    wmma_gemm_kernel<<<dim3(16, 32, 1), 256, GEMM_SMEM>>>(
        attnh, attnl, 0, woh, wol, 0, hidden, 0, hs,
        T_, H_, NH_ * HD_, (const int*)0, (const int*)0);
    // ln2
    rmsnorm_pair_kernel<<<T_, 256>>>(hidden, ln2, xn2h, xn2l, xn2f);
    // shared expert: fused gate|up GEMM (N=2048), silu-mul, down
    wmma_gemm_kernel<<<dim3(I2_ / 128, 32, 1), 256, GEMM_SMEM>>>(
        xn2h, xn2l, 0, wsguh, wsgul, 0, shgu, 0, (const float*)0,
        T_, I2_, H_, (const int*)0, (const int*)0);
    silumul_f_kernel<<<dim3(T_ * I_ / 1024, 1), 256>>>(
        shgu, shah, shal, (const int*)0);
    wmma_gemm_kernel<<<dim3(16, 32, 1), 256, GEMM_SMEM>>>(
        shah, shal, 0, sdh, sdl, 0, shout, 0, (const float*)0,
        T_, H_, I_, (const int*)0, (const int*)0);
    // router + scatter
    zero_cnt_kernel<<<1, 32>>>(cnt);
    router_kernel<<<T_ / 8, 256>>>(xn2f, rw, cnt, list, slot_e, slot_p,
                                   slot_w);
    // routed experts: fused gate|up batched GEMM, silu-mul, batched down
    wmma_gemm_kernel<<<dim3(I2_ / 128, 32, E_), 256, GEMM_SMEM>>>(
        xn2h, xn2l, 0, weguh, wegul, (size_t)H_ * I2_, mgu,
        (size_t)T_ * I2_, (const float*)0, T_, I2_, H_, cnt, list);
    silumul_f_kernel<<<dim3(T_ * I_ / 1024, E_), 256>>>(
        mgu, mah, mal, cnt);
    wmma_gemm_kernel<<<dim3(16, 32, E_), 256, GEMM_SMEM>>>(
        mah, mal, (size_t)T_ * I_, edh, edl, (size_t)I_ * H_, eout,
        (size_t)T_ * H_, (const float*)0, T_, H_, I_, cnt, (const int*)0);
    // combine
    combine_kernel<<<T_, 256>>>(hidden, shout, eout, slot_e, slot_p,
                                slot_w, out);
}